// round 13
// baseline (speedup 1.0000x reference)
#include <cuda_runtime.h>
#include <cuda_bf16.h>
#include <math.h>
#include <stdint.h>

#define NN 100000
#define NE 20000
#define NZ 500000
#define D  128
#define NL 4

// ---------------- scratch ----------------
__device__ float g_dV[NN], g_degV[NN], g_denN[NN], g_sx1[NN], g_sx2[NN];
__device__ float g_cnt[NE], g_dEs[NE], g_degE[NE], g_se1[NE], g_se2[NE];
__device__ int   g_eoff[NE + 1];
__device__ int   g_ncnt[NN], g_noff[NN + 1], g_ncur[NN];
__device__ int   g_nedge[NZ];
__device__ float g_dnp[NZ], g_gnp[NZ];
__device__ float g_x [NN * D];
__device__ float g_x0[NN * D];
__device__ float g_Xv2[NN * D];
__device__ float g_e [NE * D];
__device__ float g_Xe1[NE * D];
__device__ float g_snp[NZ];
__device__ __nv_bfloat16 g_ah[NN * D], g_al[NN * D];
__device__ __nv_bfloat16 g_ebh[NE * D], g_ebl[NE * D];
__device__ __nv_bfloat16 g_wxh[D * D], g_wxl[D * D], g_weh[D * D], g_wel[D * D];

// ---------------- mma / cp.async helpers (portable sm_80+ PTX) ----------------
__device__ __forceinline__ uint32_t s2u(const void* p) {
    uint32_t a;
    asm("{ .reg .u64 t; cvta.to.shared.u64 t, %1; cvt.u32.u64 %0, t; }" : "=r"(a) : "l"(p));
    return a;
}
__device__ __forceinline__ void ldsm4(uint32_t& r0, uint32_t& r1, uint32_t& r2, uint32_t& r3,
                                      uint32_t addr) {
    asm volatile("ldmatrix.sync.aligned.m8n8.x4.shared.b16 {%0,%1,%2,%3}, [%4];"
                 : "=r"(r0), "=r"(r1), "=r"(r2), "=r"(r3) : "r"(addr));
}
__device__ __forceinline__ void mma_bf16(float* c, const uint32_t* a, const uint32_t* b) {
    asm volatile("mma.sync.aligned.m16n8k16.row.col.f32.bf16.bf16.f32 "
                 "{%0,%1,%2,%3}, {%4,%5,%6,%7}, {%8,%9}, {%0,%1,%2,%3};"
                 : "+f"(c[0]), "+f"(c[1]), "+f"(c[2]), "+f"(c[3])
                 : "r"(a[0]), "r"(a[1]), "r"(a[2]), "r"(a[3]), "r"(b[0]), "r"(b[1]));
}
__device__ __forceinline__ void cpa16(uint32_t dst, const void* src, bool pred) {
    int sz = pred ? 16 : 0;
    asm volatile("cp.async.cg.shared.global [%0], [%1], 16, %2;"
                 :: "r"(dst), "l"(src), "r"(sz) : "memory");
}
__device__ __forceinline__ void cp_commit() {
    asm volatile("cp.async.commit_group;" ::: "memory");
}
template<int N>
__device__ __forceinline__ void cp_wait() {
    asm volatile("cp.async.wait_group %0;" :: "n"(N) : "memory");
}

// smem tiles: A = 64 rows, B = 128 rows, stride 136 bf16
#define TSTRIDE 136
#define ATILEB  (64 * TSTRIDE * 2)
#define BTILEB  (128 * TSTRIDE * 2)
#define SM_AH   0
#define SM_AL   (ATILEB)
#define SM_BH   (2 * ATILEB)
#define SM_BL   (2 * ATILEB + BTILEB)
#define SM_AW   (2 * ATILEB + 2 * BTILEB)
#define SM_BIAS (SM_AW + 1024)
#define SM_DLO  (SM_BIAS + 512)
#define SM_DHI  (SM_DLO + 512)
#define SMEM_MMA (SM_DHI + 512)

__device__ __forceinline__ void load_tileA(const __nv_bfloat16* __restrict__ g,
                                           int row0, int Mlim, uint32_t sb, int soff) {
    for (int idx = threadIdx.x; idx < 1024; idx += 256) {
        int r = idx >> 4;
        int c8 = (idx & 15) << 3;
        int gr = row0 + r;
        bool ok = gr < Mlim;
        int gs = ok ? gr : 0;
        cpa16(sb + soff + (uint32_t)((r * TSTRIDE + c8) * 2), g + (size_t)gs * D + c8, ok);
    }
}
__device__ __forceinline__ void load_tileB(const __nv_bfloat16* __restrict__ g,
                                           uint32_t sb, int soff) {
    for (int idx = threadIdx.x; idx < 2048; idx += 256) {
        int r = idx >> 4;
        int c8 = (idx & 15) << 3;
        cpa16(sb + soff + (uint32_t)((r * TSTRIDE + c8) * 2), g + (size_t)r * D + c8, true);
    }
}

struct GP {
    const __nv_bfloat16 *Ah, *Al, *Bh, *Bl;
    float* C;
    float* dlo;
    float* dhi;
    int M;
    int nblk;
};

// ---------------- GEMM core (bf16x3, fp32 acc, 64-row tile) --------------------
template<int MODE>
__device__ __forceinline__ void gemm_body(
    const __nv_bfloat16* __restrict__ Ah, const __nv_bfloat16* __restrict__ Al,
    const __nv_bfloat16* __restrict__ Bh, const __nv_bfloat16* __restrict__ Bl,
    const float* __restrict__ bias, float beta,
    float* __restrict__ C, float* __restrict__ C2, int M, int m0,
    const float* __restrict__ awrow, float* __restrict__ dlo, float* __restrict__ dhi,
    char* smem) {
    const int tid = threadIdx.x, lane = tid & 31, wid = tid >> 5;
    const int wm = wid >> 1, wn = wid & 1;
    uint32_t sb = s2u(smem);

    load_tileA(Ah, m0, M, sb, SM_AH);
    load_tileB(Bh, sb, SM_BH);
    cp_commit();
    load_tileA(Al, m0, M, sb, SM_AL);
    load_tileB(Bl, sb, SM_BL);
    cp_commit();

    float* s_aw = (float*)(smem + SM_AW);
    float* s_bias = (float*)(smem + SM_BIAS);
    float* s_lo = (float*)(smem + SM_DLO);
    float* s_hi = (float*)(smem + SM_DHI);
    if (MODE != 2) { if (tid < 256) s_aw[tid] = awrow[tid]; }
    if (MODE == 0) { if (tid < 128) s_bias[tid] = bias[tid]; }

    cp_wait<1>();
    __syncthreads();

    float acc[8][4];
#pragma unroll
    for (int nt = 0; nt < 8; nt++)
#pragma unroll
        for (int q = 0; q < 4; q++) acc[nt][q] = 0.f;

    const int a_row16 = (lane & 7) + (((lane >> 3) & 1) << 3);
    const int a_col   = ((lane >> 4) & 1) << 3;
    const int b_nin   = (lane & 7) + (((lane >> 4) & 1) << 3);
    const int b_col   = ((lane >> 3) & 1) << 3;

    const int apass[3] = {SM_AH, SM_AH, SM_AL};
    const int bpass[3] = {SM_BH, SM_BL, SM_BH};

#pragma unroll
    for (int p = 0; p < 3; p++) {
        if (p == 1) { cp_wait<0>(); __syncthreads(); }
        uint32_t aoff = sb + apass[p];
        uint32_t boff = sb + bpass[p];
#pragma unroll
        for (int ks = 0; ks < 8; ks++) {
            uint32_t a[4];
            {
                uint32_t addr = aoff + (uint32_t)(((wm * 16 + a_row16) * TSTRIDE
                                                  + ks * 16 + a_col) * 2);
                ldsm4(a[0], a[1], a[2], a[3], addr);
            }
            uint32_t b[8][2];
#pragma unroll
            for (int ntp = 0; ntp < 4; ntp++) {
                uint32_t addr = boff + (uint32_t)(((wn * 64 + ntp * 16 + b_nin) * TSTRIDE
                                                  + ks * 16 + b_col) * 2);
                ldsm4(b[2 * ntp][0], b[2 * ntp][1], b[2 * ntp + 1][0], b[2 * ntp + 1][1], addr);
            }
#pragma unroll
            for (int nt = 0; nt < 8; nt++)
                mma_bf16(acc[nt], a, b[nt]);
        }
    }

    const float ob = 1.f - beta;
    const __nv_bfloat162* sAh2 = (const __nv_bfloat162*)(smem + SM_AH);
    const __nv_bfloat162* sAl2 = (const __nv_bfloat162*)(smem + SM_AL);
    float slo[2] = {0.f, 0.f}, shi[2] = {0.f, 0.f};
#pragma unroll
    for (int nt = 0; nt < 8; nt++) {
        int col = wn * 64 + nt * 8 + (lane & 3) * 2;
        int lr0 = wm * 16 + (lane >> 2);
        int lr1 = lr0 + 8;
        int r0 = m0 + lr0;
        int r1 = m0 + lr1;
        float2 v0 = make_float2(acc[nt][0], acc[nt][1]);
        float2 v1 = make_float2(acc[nt][2], acc[nt][3]);
        if (MODE == 0) {
            float2 bb = *(const float2*)(s_bias + col);
            v0.x = fmaxf(v0.x + bb.x, 0.f); v0.y = fmaxf(v0.y + bb.y, 0.f);
            v1.x = fmaxf(v1.x + bb.x, 0.f); v1.y = fmaxf(v1.y + bb.y, 0.f);
            if (r0 < M) { *(float2*)(C + (size_t)r0 * D + col) = v0;
                          *(float2*)(C2 + (size_t)r0 * D + col) = v0; }
            if (r1 < M) { *(float2*)(C + (size_t)r1 * D + col) = v1;
                          *(float2*)(C2 + (size_t)r1 * D + col) = v1; }
        } else {
            int idx0 = (lr0 * TSTRIDE + col) >> 1;
            int idx1 = (lr1 * TSTRIDE + col) >> 1;
            __nv_bfloat162 h0 = sAh2[idx0], l0 = sAl2[idx0];
            __nv_bfloat162 h1 = sAh2[idx1], l1 = sAl2[idx1];
            float2 a0 = make_float2(__bfloat162float(h0.x) + __bfloat162float(l0.x),
                                    __bfloat162float(h0.y) + __bfloat162float(l0.y));
            float2 a1 = make_float2(__bfloat162float(h1.x) + __bfloat162float(l1.x),
                                    __bfloat162float(h1.y) + __bfloat162float(l1.y));
            v0.x = ob * a0.x + beta * v0.x; v0.y = ob * a0.y + beta * v0.y;
            v1.x = ob * a1.x + beta * v1.x; v1.y = ob * a1.y + beta * v1.y;
            if (MODE == 1) {
                v0.x = fmaxf(v0.x, 0.f); v0.y = fmaxf(v0.y, 0.f);
                v1.x = fmaxf(v1.x, 0.f); v1.y = fmaxf(v1.y, 0.f);
            }
            if (r0 < M) *(float2*)(C + (size_t)r0 * D + col) = v0;
            if (r1 < M) *(float2*)(C + (size_t)r1 * D + col) = v1;
        }
        if (MODE != 2) {
            float2 wl = *(const float2*)(s_aw + col);
            float2 wh = *(const float2*)(s_aw + 128 + col);
            slo[0] += v0.x * wl.x + v0.y * wl.y;
            shi[0] += v0.x * wh.x + v0.y * wh.y;
            slo[1] += v1.x * wl.x + v1.y * wl.y;
            shi[1] += v1.x * wh.x + v1.y * wh.y;
        }
    }
    if (MODE != 2) {
#pragma unroll
        for (int q = 0; q < 2; q++) {
            slo[q] += __shfl_xor_sync(0xffffffffu, slo[q], 1);
            slo[q] += __shfl_xor_sync(0xffffffffu, slo[q], 2);
            shi[q] += __shfl_xor_sync(0xffffffffu, shi[q], 1);
            shi[q] += __shfl_xor_sync(0xffffffffu, shi[q], 2);
        }
        if ((lane & 3) == 0) {
#pragma unroll
            for (int q = 0; q < 2; q++) {
                int lrow = wm * 16 + (lane >> 2) + q * 8;
                s_lo[lrow * 2 + wn] = slo[q];
                s_hi[lrow * 2 + wn] = shi[q];
            }
        }
        __syncthreads();
        if (tid < 64) {
            int grow = m0 + tid;
            if (grow < M) {
                dlo[grow] = s_lo[tid * 2] + s_lo[tid * 2 + 1];
                dhi[grow] = s_hi[tid * 2] + s_hi[tid * 2 + 1];
            }
        }
    }
}

__global__ void __launch_bounds__(256, 2)
k_gemm0(const __nv_bfloat16* __restrict__ Ah, const __nv_bfloat16* __restrict__ Al,
        const __nv_bfloat16* __restrict__ Bh, const __nv_bfloat16* __restrict__ Bl,
        const float* __restrict__ bias, float* __restrict__ C, float* __restrict__ C2,
        int M, const float* __restrict__ awrow, float* __restrict__ dlo,
        float* __restrict__ dhi) {
    extern __shared__ char smem[];
    gemm_body<0>(Ah, Al, Bh, Bl, bias, 0.f, C, C2, M, blockIdx.x * 64,
                 awrow, dlo, dhi, smem);
}
template<int MODE>
__global__ void __launch_bounds__(256, 2)
k_gemm2(GP ga, GP gb, float beta, const float* __restrict__ awrow) {
    extern __shared__ char smem[];
    bool isA = blockIdx.x < (unsigned)ga.nblk;
    GP g = isA ? ga : gb;
    int m0 = (isA ? blockIdx.x : blockIdx.x - ga.nblk) * 64;
    gemm_body<MODE>(g.Ah, g.Al, g.Bh, g.Bl, nullptr, beta, g.C, nullptr,
                    g.M, m0, awrow, g.dlo, g.dhi, smem);
}

// ---------------- conversions ----------------
__global__ void k_cvt_rows(const float* __restrict__ src, __nv_bfloat16* __restrict__ hi,
                           __nv_bfloat16* __restrict__ lo, int n4) {
    int i = blockIdx.x * blockDim.x + threadIdx.x;
    if (i >= n4) return;
    float4 v = ((const float4*)src)[i];
    __nv_bfloat16 h0 = __float2bfloat16(v.x), h1 = __float2bfloat16(v.y);
    __nv_bfloat16 h2 = __float2bfloat16(v.z), h3 = __float2bfloat16(v.w);
    __nv_bfloat162 a, b;
    a.x = h0; a.y = h1; b.x = h2; b.y = h3;
    ((__nv_bfloat162*)hi)[2 * i] = a; ((__nv_bfloat162*)hi)[2 * i + 1] = b;
    a.x = __float2bfloat16(v.x - __bfloat162float(h0));
    a.y = __float2bfloat16(v.y - __bfloat162float(h1));
    b.x = __float2bfloat16(v.z - __bfloat162float(h2));
    b.y = __float2bfloat16(v.w - __bfloat162float(h3));
    ((__nv_bfloat162*)lo)[2 * i] = a; ((__nv_bfloat162*)lo)[2 * i + 1] = b;
}
__global__ void k_cvt_w2(const float* __restrict__ Wx, const float* __restrict__ We) {
    int i = blockIdx.x * blockDim.x + threadIdx.x;
    if (i >= 2 * D * D) return;
    const float* W = (i < D * D) ? Wx : We;
    __nv_bfloat16* hi = (i < D * D) ? g_wxh : g_weh;
    __nv_bfloat16* lo = (i < D * D) ? g_wxl : g_wel;
    int j = (i < D * D) ? i : i - D * D;
    int n = j >> 7, k = j & 127;
    float v = W[(size_t)k * D + n];
    __nv_bfloat16 h = __float2bfloat16(v);
    hi[j] = h;
    lo[j] = __float2bfloat16(v - __bfloat162float(h));
}
__global__ void k_cvt_w(const float* __restrict__ W, __nv_bfloat16* __restrict__ hi,
                        __nv_bfloat16* __restrict__ lo) {
    int i = blockIdx.x * blockDim.x + threadIdx.x;
    if (i >= D * D) return;
    int n = i >> 7, k = i & 127;
    float v = W[(size_t)k * D + n];
    __nv_bfloat16 h = __float2bfloat16(v);
    hi[i] = h;
    lo[i] = __float2bfloat16(v - __bfloat162float(h));
}

// ---------------- degrees / CSR setup ----------------
__global__ void k_deg1(const int* __restrict__ nodes, const int* __restrict__ edges) {
    int i = blockIdx.x * blockDim.x + threadIdx.x;
    if (i >= NZ) return;
    atomicAdd(&g_dV[nodes[i]], 1.f);
    atomicAdd(&g_cnt[edges[i]], 1.f);
    atomicAdd(&g_ncnt[nodes[i]], 1);
}
__global__ void k_deg2(const int* __restrict__ nodes, const int* __restrict__ edges) {
    int i = blockIdx.x * blockDim.x + threadIdx.x;
    if (i >= NZ) return;
    atomicAdd(&g_dEs[edges[i]], g_dV[nodes[i]]);
}
__global__ void k_deg3() {
    int i = blockIdx.x * blockDim.x + threadIdx.x;
    if (i < NN) { float d = g_dV[i]; g_degV[i] = (d > 0.f) ? rsqrtf(d) : 1.f; }
    if (i < NE) {
        float de = g_dEs[i] / fmaxf(g_cnt[i], 1.f);
        g_degE[i] = (de > 0.f) ? rsqrtf(de) : 1.f;
    }
}
__global__ void k_eoff2(const int* __restrict__ edges) {
    int i = blockIdx.x * blockDim.x + threadIdx.x;
    if (i >= NZ) return;
    int e1 = edges[i];
    int e0 = (i == 0) ? -1 : edges[i - 1];
    for (int e = e0 + 1; e <= e1; e++) g_eoff[e] = i;
    if (i == NZ - 1)
        for (int e = e1 + 1; e <= NE; e++) g_eoff[e] = NZ;
}
__global__ void k_scan() {
    __shared__ int warpsum[32];
    __shared__ int s_run;
    const int tid = threadIdx.x, lane = tid & 31, wid = tid >> 5;
    if (tid == 0) s_run = 0;
    __syncthreads();
    for (int base = 0; base < NN; base += 1024) {
        int v = (base + tid < NN) ? g_ncnt[base + tid] : 0;
        int x = v;
#pragma unroll
        for (int o = 1; o < 32; o <<= 1) {
            int y = __shfl_up_sync(0xffffffffu, x, o);
            if (lane >= o) x += y;
        }
        if (lane == 31) warpsum[wid] = x;
        __syncthreads();
        if (wid == 0) {
            int s = warpsum[lane];
#pragma unroll
            for (int o = 1; o < 32; o <<= 1) {
                int y = __shfl_up_sync(0xffffffffu, s, o);
                if (lane >= o) s += y;
            }
            warpsum[lane] = s;
        }
        __syncthreads();
        int pref = (wid > 0) ? warpsum[wid - 1] : 0;
        int total = warpsum[31];
        int run = s_run;
        if (base + tid < NN) {
            g_noff[base + tid] = run + pref + x - v;
            g_ncur[base + tid] = run + pref + x - v;
        }
        __syncthreads();
        if (tid == 0) s_run += total;
        __syncthreads();
    }
    if (tid == 0) g_noff[NN] = NZ;
}
__global__ void k_scatter(const int* __restrict__ nodes, const int* __restrict__ edges,
                          const float* __restrict__ dn, const float* __restrict__ gn) {
    int i = blockIdx.x * blockDim.x + threadIdx.x;
    if (i >= NZ) return;
    int nd = nodes[i];
    int p = atomicAdd(&g_ncur[nd], 1);
    g_nedge[p] = edges[i];
    g_dnp[p] = dn[i];
    g_gnp[p] = gn[i];
}

// ---------------- rowdot (layer-0 e only) ----------------
__global__ void k_rowdot(const float* __restrict__ Mx, const float* __restrict__ vlo,
                         const float* __restrict__ vhi, float* __restrict__ olo,
                         float* __restrict__ ohi, int rows) {
    int t = blockIdx.x * blockDim.x + threadIdx.x;
    int w = t >> 5, lane = t & 31;
    if (w >= rows) return;
    float4 a  = ((const float4*)(Mx + (size_t)w * D))[lane];
    float4 l4 = ((const float4*)vlo)[lane];
    float4 h4 = ((const float4*)vhi)[lane];
    float slo = a.x * l4.x + a.y * l4.y + a.z * l4.z + a.w * l4.w;
    float shi = a.x * h4.x + a.y * h4.y + a.z * h4.z + a.w * h4.w;
#pragma unroll
    for (int o = 16; o > 0; o >>= 1) {
        slo += __shfl_xor_sync(0xffffffffu, slo, o);
        shi += __shfl_xor_sync(0xffffffffu, shi, o);
    }
    if (lane == 0) { olo[w] = slo; ohi[w] = shi; }
}

// ---------------- K1: node pass A — snp/denN + Xv2s ---------------------------
__global__ void __launch_bounds__(256)
k_nodeA(const float* pab, const float* pwdw, const float* pwdb,
        const float* pwgw, const float* pwgb) {
    int t = blockIdx.x * blockDim.x + threadIdx.x;
    int w = t >> 5, lane = t & 31;
    if (w >= NN) return;
    float cst = *pab + *pwdb + *pwgb;
    float wdw = *pwdw, wgw = *pwgw;
    int o0 = g_noff[w], o1 = g_noff[w + 1];
    float base = g_sx2[w] + cst;
    float4 acc = make_float4(0.f, 0.f, 0.f, 0.f);
    float4 acc2 = make_float4(0.f, 0.f, 0.f, 0.f);
    float den = 0.f;
    for (int j0 = o0; j0 < o1; j0 += 32) {
        int j = j0 + lane;
        int edl = 0;
        float wexp = 0.f;
        if (j < o1) {
            edl = __ldg(g_nedge + j);
            wexp = __expf(g_se2[edl] + base + g_dnp[j] * wdw + g_gnp[j] * wgw);
            g_snp[j] = wexp;
        }
        den += wexp;
        int cnt = min(32, o1 - j0);
        int k = 0;
        for (; k + 1 < cnt; k += 2) {
            float w0 = __shfl_sync(0xffffffffu, wexp, k);
            int  ed0 = __shfl_sync(0xffffffffu, edl, k);
            float w1 = __shfl_sync(0xffffffffu, wexp, k + 1);
            int  ed1 = __shfl_sync(0xffffffffu, edl, k + 1);
            float4 e0 = ((const float4*)(g_e + (size_t)ed0 * D))[lane];
            float4 e1 = ((const float4*)(g_e + (size_t)ed1 * D))[lane];
            acc.x = fmaf(e0.x, w0, acc.x); acc.y = fmaf(e0.y, w0, acc.y);
            acc.z = fmaf(e0.z, w0, acc.z); acc.w = fmaf(e0.w, w0, acc.w);
            acc2.x = fmaf(e1.x, w1, acc2.x); acc2.y = fmaf(e1.y, w1, acc2.y);
            acc2.z = fmaf(e1.z, w1, acc2.z); acc2.w = fmaf(e1.w, w1, acc2.w);
        }
        if (k < cnt) {
            float w0 = __shfl_sync(0xffffffffu, wexp, k);
            int  ed0 = __shfl_sync(0xffffffffu, edl, k);
            float4 e0 = ((const float4*)(g_e + (size_t)ed0 * D))[lane];
            acc.x = fmaf(e0.x, w0, acc.x); acc.y = fmaf(e0.y, w0, acc.y);
            acc.z = fmaf(e0.z, w0, acc.z); acc.w = fmaf(e0.w, w0, acc.w);
        }
    }
#pragma unroll
    for (int o = 16; o > 0; o >>= 1) den += __shfl_xor_sync(0xffffffffu, den, o);
    if (lane == 0) g_denN[w] = den;
    float s = (o1 > o0) ? g_degV[w] / den : 0.f;
    ((float4*)(g_Xv2 + (size_t)w * D))[lane] =
        make_float4((acc.x + acc2.x) * s, (acc.y + acc2.y) * s,
                    (acc.z + acc2.z) * s, (acc.w + acc2.w) * s);
}

// ---------------- bf16 split helper ----------------
__device__ __forceinline__ void split_store4(__nv_bfloat16* hi, __nv_bfloat16* lo,
                                             int i, float4 r) {
    __nv_bfloat16 h0 = __float2bfloat16(r.x), h1 = __float2bfloat16(r.y);
    __nv_bfloat16 h2 = __float2bfloat16(r.z), h3 = __float2bfloat16(r.w);
    __nv_bfloat162 a, b;
    a.x = h0; a.y = h1; b.x = h2; b.y = h3;
    ((__nv_bfloat162*)hi)[2 * i] = a; ((__nv_bfloat162*)hi)[2 * i + 1] = b;
    a.x = __float2bfloat16(r.x - __bfloat162float(h0));
    a.y = __float2bfloat16(r.y - __bfloat162float(h1));
    b.x = __float2bfloat16(r.z - __bfloat162float(h2));
    b.y = __float2bfloat16(r.w - __bfloat162float(h3));
    ((__nv_bfloat162*)lo)[2 * i] = a; ((__nv_bfloat162*)lo)[2 * i + 1] = b;
}

// ---------------- K2: edge pass — sv inline, dual gather, Xe1s + ei -----------
__global__ void __launch_bounds__(256)
k_edge(const int* __restrict__ nodes,
       const float* __restrict__ dv, const float* __restrict__ gv,
       const float* __restrict__ e0,
       const float* pab, const float* pwdw, const float* pwdb,
       const float* pwgw, const float* pwgb) {
    int t = blockIdx.x * blockDim.x + threadIdx.x;
    int w = t >> 5, lane = t & 31;
    if (w >= NE) return;
    float cst = *pab + *pwdb + *pwgb;
    float wdw = *pwdw, wgw = *pwgw;
    int o0 = g_eoff[w], o1 = g_eoff[w + 1];
    float base = g_se1[w] + cst;
    float4 accA = make_float4(0.f, 0.f, 0.f, 0.f);
    float4 accB = make_float4(0.f, 0.f, 0.f, 0.f);
    float den = 0.f;
    for (int i0 = o0; i0 < o1; i0 += 32) {
        int i = i0 + lane;
        int ndl = 0;
        float wexp = 0.f;
        if (i < o1) {
            ndl = __ldg(nodes + i);
            wexp = __expf(g_sx1[ndl] + base + dv[i] * wdw + gv[i] * wgw);
        }
        den += wexp;
        int cnt = min(32, o1 - i0);
        for (int k = 0; k < cnt; k++) {
            float w0 = __shfl_sync(0xffffffffu, wexp, k);
            int  nd0 = __shfl_sync(0xffffffffu, ndl, k);
            float4 xr = ((const float4*)(g_x + (size_t)nd0 * D))[lane];
            float4 vr = ((const float4*)(g_Xv2 + (size_t)nd0 * D))[lane];
            accA.x = fmaf(xr.x, w0, accA.x); accA.y = fmaf(xr.y, w0, accA.y);
            accA.z = fmaf(xr.z, w0, accA.z); accA.w = fmaf(xr.w, w0, accA.w);
            accB.x = fmaf(vr.x, w0, accB.x); accB.y = fmaf(vr.y, w0, accB.y);
            accB.z = fmaf(vr.z, w0, accB.z); accB.w = fmaf(vr.w, w0, accB.w);
        }
    }
#pragma unroll
    for (int o = 16; o > 0; o >>= 1) den += __shfl_xor_sync(0xffffffffu, den, o);
    float de = g_degE[w];
    float s1 = (o1 > o0) ? de / den : 0.f;       // Xe1s scale
    float s2 = (o1 > o0) ? 0.45f * de / den : 0.f; // ei Xe2 term scale
    float4 xe1 = make_float4(accA.x * s1, accA.y * s1, accA.z * s1, accA.w * s1);
    ((float4*)(g_Xe1 + (size_t)w * D))[lane] = xe1;
    float4 ev = ((const float4*)(e0 + (size_t)w * D))[lane];
    float4 r;
    r.x = s2 * accB.x + 0.45f * xe1.x + 0.1f * ev.x;
    r.y = s2 * accB.y + 0.45f * xe1.y + 0.1f * ev.y;
    r.z = s2 * accB.z + 0.45f * xe1.z + 0.1f * ev.z;
    r.w = s2 * accB.w + 0.45f * xe1.w + 0.1f * ev.w;
    split_store4(g_ebh, g_ebl, w * 32 + lane, r);
}

// ---------------- K3: node pass B — Xv1 gather + mix_x + split ----------------
__global__ void __launch_bounds__(256)
k_nodeB() {
    int t = blockIdx.x * blockDim.x + threadIdx.x;
    int w = t >> 5, lane = t & 31;
    if (w >= NN) return;
    int o0 = g_noff[w], o1 = g_noff[w + 1];
    float4 acc = make_float4(0.f, 0.f, 0.f, 0.f);
    float4 acc2 = make_float4(0.f, 0.f, 0.f, 0.f);
    int j = o0;
    for (; j + 1 < o1; j += 2) {
        int ed0 = __ldg(g_nedge + j), ed1 = __ldg(g_nedge + j + 1);
        float w0 = g_snp[j], w1 = g_snp[j + 1];
        float4 e0r = ((const float4*)(g_Xe1 + (size_t)ed0 * D))[lane];
        float4 e1r = ((const float4*)(g_Xe1 + (size_t)ed1 * D))[lane];
        acc.x = fmaf(e0r.x, w0, acc.x); acc.y = fmaf(e0r.y, w0, acc.y);
        acc.z = fmaf(e0r.z, w0, acc.z); acc.w = fmaf(e0r.w, w0, acc.w);
        acc2.x = fmaf(e1r.x, w1, acc2.x); acc2.y = fmaf(e1r.y, w1, acc2.y);
        acc2.z = fmaf(e1r.z, w1, acc2.z); acc2.w = fmaf(e1r.w, w1, acc2.w);
    }
    if (j < o1) {
        int ed = __ldg(g_nedge + j);
        float wn = g_snp[j];
        float4 xr = ((const float4*)(g_Xe1 + (size_t)ed * D))[lane];
        acc.x = fmaf(xr.x, wn, acc.x); acc.y = fmaf(xr.y, wn, acc.y);
        acc.z = fmaf(xr.z, wn, acc.z); acc.w = fmaf(xr.w, wn, acc.w);
    }
    float s = (o1 > o0) ? 1.f / g_denN[w] : 0.f;
    float sc = 0.45f * g_degV[w] * s;
    float4 v2 = ((const float4*)(g_Xv2 + (size_t)w * D))[lane];
    float4 x0 = ((const float4*)(g_x0 + (size_t)w * D))[lane];
    float4 r;
    r.x = sc * (acc.x + acc2.x) + 0.45f * v2.x + 0.1f * x0.x;
    r.y = sc * (acc.y + acc2.y) + 0.45f * v2.y + 0.1f * x0.y;
    r.z = sc * (acc.z + acc2.z) + 0.45f * v2.z + 0.1f * x0.z;
    r.w = sc * (acc.w + acc2.w) + 0.45f * v2.w + 0.1f * x0.w;
    split_store4(g_ah, g_al, w * 32 + lane, r);
}

// ---------------- launch ----------------
extern "C" void kernel_launch(void* const* d_in, const int* in_sizes, int n_in,
                              void* d_out, int out_size) {
    const float* x_in = (const float*)d_in[0];
    const float* e_in = (const float*)d_in[1];
    const int*   hei  = (const int*)d_in[2];
    const int*   nodes = hei;
    const int*   edges = hei + NZ;
    const float* dv2e = (const float*)d_in[3];
    const float* gv2e = (const float*)d_in[4];
    const float* de2v = (const float*)d_in[5];
    const float* ge2v = (const float*)d_in[6];
    const float* W0   = (const float*)d_in[7];
    const float* b0   = (const float*)d_in[8];
    const float* Wn   = (const float*)d_in[9];
    const float* We   = (const float*)d_in[10];
    const float* aw   = (const float*)d_in[11];
    const float* ab   = (const float*)d_in[12];
    const float* wdw  = (const float*)d_in[13];
    const float* wdb  = (const float*)d_in[14];
    const float* wgw  = (const float*)d_in[15];
    const float* wgb  = (const float*)d_in[16];
    float* out = (float*)d_out;

    cudaFuncSetAttribute(k_gemm0, cudaFuncAttributeMaxDynamicSharedMemorySize, SMEM_MMA);
    cudaFuncSetAttribute(k_gemm2<1>, cudaFuncAttributeMaxDynamicSharedMemorySize, SMEM_MMA);
    cudaFuncSetAttribute(k_gemm2<2>, cudaFuncAttributeMaxDynamicSharedMemorySize, SMEM_MMA);

    void *pdV, *pcnt, *pdEs, *pncnt;
    void *px, *px0, *pe, *psx1, *psx2, *pse1, *pse2;
    void *pah, *pal, *pebh, *pebl, *pwxh, *pwxl, *pweh, *pwel;
    cudaGetSymbolAddress(&pdV, g_dV);     cudaGetSymbolAddress(&pcnt, g_cnt);
    cudaGetSymbolAddress(&pdEs, g_dEs);   cudaGetSymbolAddress(&pncnt, g_ncnt);
    cudaGetSymbolAddress(&px, g_x);       cudaGetSymbolAddress(&px0, g_x0);
    cudaGetSymbolAddress(&pe, g_e);
    cudaGetSymbolAddress(&psx1, g_sx1);   cudaGetSymbolAddress(&psx2, g_sx2);
    cudaGetSymbolAddress(&pse1, g_se1);   cudaGetSymbolAddress(&pse2, g_se2);
    cudaGetSymbolAddress(&pah, g_ah);     cudaGetSymbolAddress(&pal, g_al);
    cudaGetSymbolAddress(&pebh, g_ebh);   cudaGetSymbolAddress(&pebl, g_ebl);
    cudaGetSymbolAddress(&pwxh, g_wxh);   cudaGetSymbolAddress(&pwxl, g_wxl);
    cudaGetSymbolAddress(&pweh, g_weh);   cudaGetSymbolAddress(&pwel, g_wel);

    const int B = 256;
    const int gNZ   = (NZ + B - 1) / B;
    const int gNN   = (NN + B - 1) / B;
    const int gNW   = (NN * 32 + B - 1) / B;
    const int gEW   = (NE * 32 + B - 1) / B;
    const int gXT   = (NN + 63) / 64;
    const int gET   = (NE + 63) / 64;

    // ---- one-time setup ----
    cudaMemsetAsync(pdV, 0, NN * 4, 0);
    cudaMemsetAsync(pcnt, 0, NE * 4, 0);
    cudaMemsetAsync(pdEs, 0, NE * 4, 0);
    cudaMemsetAsync(pncnt, 0, NN * 4, 0);
    k_deg1<<<gNZ, B>>>(nodes, edges);
    k_deg2<<<gNZ, B>>>(nodes, edges);
    k_deg3<<<gNN, B>>>();
    k_eoff2<<<gNZ, B>>>(edges);
    k_scan<<<1, 1024>>>();
    k_scatter<<<gNZ, B>>>(nodes, edges, de2v, ge2v);

    k_cvt_rows<<<(NN * D / 4 + B - 1) / B, B>>>(x_in, (__nv_bfloat16*)pah, (__nv_bfloat16*)pal,
                                                NN * D / 4);
    k_cvt_w<<<(D * D + B - 1) / B, B>>>(W0, (__nv_bfloat16*)pwxh, (__nv_bfloat16*)pwxl);
    k_gemm0<<<gXT, 256, SMEM_MMA>>>((__nv_bfloat16*)pah, (__nv_bfloat16*)pal,
                                    (__nv_bfloat16*)pwxh, (__nv_bfloat16*)pwxl,
                                    b0, (float*)px, (float*)px0, NN,
                                    aw, (float*)psx1, (float*)psx2);
    cudaMemcpyAsync(pe, e_in, (size_t)NE * D * 4, cudaMemcpyDeviceToDevice, 0);
    k_rowdot<<<(NE * 32 + B - 1) / B, B>>>(e_in, aw, aw + D, (float*)pse2, (float*)pse1, NE);

    bool both = (out_size >= (NN + NE) * D);

    for (int l = 0; l < NL; l++) {
        float beta = logf(0.5f / (float)(l + 1) + 1.f);

        k_nodeA<<<gNW, B>>>(ab + l, wdw + l, wdb + l, wgw + l, wgb + l);
        k_edge<<<gEW, B>>>(nodes, dv2e, gv2e, e_in,
                           ab + l, wdw + l, wdb + l, wgw + l, wgb + l);
        k_nodeB<<<gNW, B>>>();

        k_cvt_w2<<<(2 * D * D + B - 1) / B, B>>>(Wn + (size_t)l * D * D,
                                                 We + (size_t)l * D * D);

        GP gx, ge;
        gx.Ah = (__nv_bfloat16*)pah; gx.Al = (__nv_bfloat16*)pal;
        gx.Bh = (__nv_bfloat16*)pwxh; gx.Bl = (__nv_bfloat16*)pwxl;
        gx.M = NN; gx.nblk = gXT;
        gx.dlo = (float*)psx1; gx.dhi = (float*)psx2;
        ge.Ah = (__nv_bfloat16*)pebh; ge.Al = (__nv_bfloat16*)pebl;
        ge.Bh = (__nv_bfloat16*)pweh; ge.Bl = (__nv_bfloat16*)pwel;
        ge.M = NE; ge.nblk = gET;
        ge.dlo = (float*)pse2; ge.dhi = (float*)pse1;

        if (l < NL - 1) {
            gx.C = (float*)px;
            ge.C = (float*)pe;
            const float* awn = aw + (size_t)(l + 1) * 2 * D;
            k_gemm2<1><<<gXT + gET, 256, SMEM_MMA>>>(gx, ge, beta, awn);
        } else {
            gx.C = out;
            ge.C = both ? out + (size_t)NN * D : (float*)pe;
            k_gemm2<2><<<gXT + gET, 256, SMEM_MMA>>>(gx, ge, beta, nullptr);
        }
    }
}

// round 14
// speedup vs baseline: 1.0537x; 1.0537x over previous
#include <cuda_runtime.h>
#include <cuda_bf16.h>
#include <math.h>
#include <stdint.h>

#define NN 100000
#define NE 20000
#define NZ 500000
#define D  128
#define NL 4

// ---------------- scratch ----------------
__device__ float g_degV[NN], g_denN[NN], g_sx1[NN], g_sx2[NN];
__device__ float g_degE[NE], g_denE[NE], g_se1[NE], g_se2[NE];
__device__ int   g_eoff[NE + 1];
__device__ int   g_ncnt[NN], g_noff[NN + 1], g_ncur[NN];
__device__ int   g_nedge[NZ];
__device__ float g_dnp[NZ], g_gnp[NZ];
__device__ float g_x [NN * D];
__device__ float g_x0[NN * D];
__device__ float g_Xv2[NN * D];
__device__ float g_e [NE * D];
__device__ float g_Xe1[NE * D];
__device__ float g_sv[NZ], g_snp[NZ];
__device__ __nv_bfloat16 g_ah[NN * D], g_al[NN * D];
__device__ __nv_bfloat16 g_ebh[NE * D], g_ebl[NE * D];
__device__ __nv_bfloat16 g_wxh[D * D], g_wxl[D * D], g_weh[D * D], g_wel[D * D];

// ---------------- mma / cp.async helpers (portable sm_80+ PTX) ----------------
__device__ __forceinline__ uint32_t s2u(const void* p) {
    uint32_t a;
    asm("{ .reg .u64 t; cvta.to.shared.u64 t, %1; cvt.u32.u64 %0, t; }" : "=r"(a) : "l"(p));
    return a;
}
__device__ __forceinline__ void ldsm4(uint32_t& r0, uint32_t& r1, uint32_t& r2, uint32_t& r3,
                                      uint32_t addr) {
    asm volatile("ldmatrix.sync.aligned.m8n8.x4.shared.b16 {%0,%1,%2,%3}, [%4];"
                 : "=r"(r0), "=r"(r1), "=r"(r2), "=r"(r3) : "r"(addr));
}
__device__ __forceinline__ void mma_bf16(float* c, const uint32_t* a, const uint32_t* b) {
    asm volatile("mma.sync.aligned.m16n8k16.row.col.f32.bf16.bf16.f32 "
                 "{%0,%1,%2,%3}, {%4,%5,%6,%7}, {%8,%9}, {%0,%1,%2,%3};"
                 : "+f"(c[0]), "+f"(c[1]), "+f"(c[2]), "+f"(c[3])
                 : "r"(a[0]), "r"(a[1]), "r"(a[2]), "r"(a[3]), "r"(b[0]), "r"(b[1]));
}
__device__ __forceinline__ void cpa16(uint32_t dst, const void* src, bool pred) {
    int sz = pred ? 16 : 0;
    asm volatile("cp.async.cg.shared.global [%0], [%1], 16, %2;"
                 :: "r"(dst), "l"(src), "r"(sz) : "memory");
}
__device__ __forceinline__ void cp_commit() {
    asm volatile("cp.async.commit_group;" ::: "memory");
}
template<int N>
__device__ __forceinline__ void cp_wait() {
    asm volatile("cp.async.wait_group %0;" :: "n"(N) : "memory");
}

// smem tiles: A = 64 rows, B = 128 rows, stride 136 bf16
#define TSTRIDE 136
#define ATILEB  (64 * TSTRIDE * 2)
#define BTILEB  (128 * TSTRIDE * 2)
#define SM_AH   0
#define SM_AL   (ATILEB)
#define SM_BH   (2 * ATILEB)
#define SM_BL   (2 * ATILEB + BTILEB)
#define SM_AW   (2 * ATILEB + 2 * BTILEB)
#define SM_BIAS (SM_AW + 1024)
#define SM_DLO  (SM_BIAS + 512)
#define SM_DHI  (SM_DLO + 512)
#define SMEM_MMA (SM_DHI + 512)

__device__ __forceinline__ void load_tileA(const __nv_bfloat16* __restrict__ g,
                                           int row0, int Mlim, uint32_t sb, int soff) {
    for (int idx = threadIdx.x; idx < 1024; idx += 256) {
        int r = idx >> 4;
        int c8 = (idx & 15) << 3;
        int gr = row0 + r;
        bool ok = gr < Mlim;
        int gs = ok ? gr : 0;
        cpa16(sb + soff + (uint32_t)((r * TSTRIDE + c8) * 2), g + (size_t)gs * D + c8, ok);
    }
}
__device__ __forceinline__ void load_tileB(const __nv_bfloat16* __restrict__ g,
                                           uint32_t sb, int soff) {
    for (int idx = threadIdx.x; idx < 2048; idx += 256) {
        int r = idx >> 4;
        int c8 = (idx & 15) << 3;
        cpa16(sb + soff + (uint32_t)((r * TSTRIDE + c8) * 2), g + (size_t)r * D + c8, true);
    }
}

struct GP {
    const __nv_bfloat16 *Ah, *Al, *Bh, *Bl;
    float* C;
    float* dlo;
    float* dhi;
    int M;
    int nblk;
};

// ---------------- GEMM core (bf16x3, fp32 acc, 64-row tile) --------------------
template<int MODE>
__device__ __forceinline__ void gemm_body(
    const __nv_bfloat16* __restrict__ Ah, const __nv_bfloat16* __restrict__ Al,
    const __nv_bfloat16* __restrict__ Bh, const __nv_bfloat16* __restrict__ Bl,
    const float* __restrict__ bias, float beta,
    float* __restrict__ C, float* __restrict__ C2, int M, int m0,
    const float* __restrict__ awrow, float* __restrict__ dlo, float* __restrict__ dhi,
    char* smem) {
    const int tid = threadIdx.x, lane = tid & 31, wid = tid >> 5;
    const int wm = wid >> 1, wn = wid & 1;
    uint32_t sb = s2u(smem);

    load_tileA(Ah, m0, M, sb, SM_AH);
    load_tileB(Bh, sb, SM_BH);
    cp_commit();
    load_tileA(Al, m0, M, sb, SM_AL);
    load_tileB(Bl, sb, SM_BL);
    cp_commit();

    float* s_aw = (float*)(smem + SM_AW);
    float* s_bias = (float*)(smem + SM_BIAS);
    float* s_lo = (float*)(smem + SM_DLO);
    float* s_hi = (float*)(smem + SM_DHI);
    if (MODE != 2) { if (tid < 256) s_aw[tid] = awrow[tid]; }
    if (MODE == 0) { if (tid < 128) s_bias[tid] = bias[tid]; }

    cp_wait<1>();
    __syncthreads();

    float acc[8][4];
#pragma unroll
    for (int nt = 0; nt < 8; nt++)
#pragma unroll
        for (int q = 0; q < 4; q++) acc[nt][q] = 0.f;

    const int a_row16 = (lane & 7) + (((lane >> 3) & 1) << 3);
    const int a_col   = ((lane >> 4) & 1) << 3;
    const int b_nin   = (lane & 7) + (((lane >> 4) & 1) << 3);
    const int b_col   = ((lane >> 3) & 1) << 3;

    const int apass[3] = {SM_AH, SM_AH, SM_AL};
    const int bpass[3] = {SM_BH, SM_BL, SM_BH};

#pragma unroll
    for (int p = 0; p < 3; p++) {
        if (p == 1) { cp_wait<0>(); __syncthreads(); }
        uint32_t aoff = sb + apass[p];
        uint32_t boff = sb + bpass[p];
#pragma unroll
        for (int ks = 0; ks < 8; ks++) {
            uint32_t a[4];
            {
                uint32_t addr = aoff + (uint32_t)(((wm * 16 + a_row16) * TSTRIDE
                                                  + ks * 16 + a_col) * 2);
                ldsm4(a[0], a[1], a[2], a[3], addr);
            }
            uint32_t b[8][2];
#pragma unroll
            for (int ntp = 0; ntp < 4; ntp++) {
                uint32_t addr = boff + (uint32_t)(((wn * 64 + ntp * 16 + b_nin) * TSTRIDE
                                                  + ks * 16 + b_col) * 2);
                ldsm4(b[2 * ntp][0], b[2 * ntp][1], b[2 * ntp + 1][0], b[2 * ntp + 1][1], addr);
            }
#pragma unroll
            for (int nt = 0; nt < 8; nt++)
                mma_bf16(acc[nt], a, b[nt]);
        }
    }

    const float ob = 1.f - beta;
    const __nv_bfloat162* sAh2 = (const __nv_bfloat162*)(smem + SM_AH);
    const __nv_bfloat162* sAl2 = (const __nv_bfloat162*)(smem + SM_AL);
    float slo[2] = {0.f, 0.f}, shi[2] = {0.f, 0.f};
#pragma unroll
    for (int nt = 0; nt < 8; nt++) {
        int col = wn * 64 + nt * 8 + (lane & 3) * 2;
        int lr0 = wm * 16 + (lane >> 2);
        int lr1 = lr0 + 8;
        int r0 = m0 + lr0;
        int r1 = m0 + lr1;
        float2 v0 = make_float2(acc[nt][0], acc[nt][1]);
        float2 v1 = make_float2(acc[nt][2], acc[nt][3]);
        if (MODE == 0) {
            float2 bb = *(const float2*)(s_bias + col);
            v0.x = fmaxf(v0.x + bb.x, 0.f); v0.y = fmaxf(v0.y + bb.y, 0.f);
            v1.x = fmaxf(v1.x + bb.x, 0.f); v1.y = fmaxf(v1.y + bb.y, 0.f);
            if (r0 < M) { *(float2*)(C + (size_t)r0 * D + col) = v0;
                          *(float2*)(C2 + (size_t)r0 * D + col) = v0; }
            if (r1 < M) { *(float2*)(C + (size_t)r1 * D + col) = v1;
                          *(float2*)(C2 + (size_t)r1 * D + col) = v1; }
        } else {
            int idx0 = (lr0 * TSTRIDE + col) >> 1;
            int idx1 = (lr1 * TSTRIDE + col) >> 1;
            __nv_bfloat162 h0 = sAh2[idx0], l0 = sAl2[idx0];
            __nv_bfloat162 h1 = sAh2[idx1], l1 = sAl2[idx1];
            float2 a0 = make_float2(__bfloat162float(h0.x) + __bfloat162float(l0.x),
                                    __bfloat162float(h0.y) + __bfloat162float(l0.y));
            float2 a1 = make_float2(__bfloat162float(h1.x) + __bfloat162float(l1.x),
                                    __bfloat162float(h1.y) + __bfloat162float(l1.y));
            v0.x = ob * a0.x + beta * v0.x; v0.y = ob * a0.y + beta * v0.y;
            v1.x = ob * a1.x + beta * v1.x; v1.y = ob * a1.y + beta * v1.y;
            if (MODE == 1) {
                v0.x = fmaxf(v0.x, 0.f); v0.y = fmaxf(v0.y, 0.f);
                v1.x = fmaxf(v1.x, 0.f); v1.y = fmaxf(v1.y, 0.f);
            }
            if (r0 < M) *(float2*)(C + (size_t)r0 * D + col) = v0;
            if (r1 < M) *(float2*)(C + (size_t)r1 * D + col) = v1;
        }
        if (MODE != 2) {
            float2 wl = *(const float2*)(s_aw + col);
            float2 wh = *(const float2*)(s_aw + 128 + col);
            slo[0] += v0.x * wl.x + v0.y * wl.y;
            shi[0] += v0.x * wh.x + v0.y * wh.y;
            slo[1] += v1.x * wl.x + v1.y * wl.y;
            shi[1] += v1.x * wh.x + v1.y * wh.y;
        }
    }
    if (MODE != 2) {
#pragma unroll
        for (int q = 0; q < 2; q++) {
            slo[q] += __shfl_xor_sync(0xffffffffu, slo[q], 1);
            slo[q] += __shfl_xor_sync(0xffffffffu, slo[q], 2);
            shi[q] += __shfl_xor_sync(0xffffffffu, shi[q], 1);
            shi[q] += __shfl_xor_sync(0xffffffffu, shi[q], 2);
        }
        if ((lane & 3) == 0) {
#pragma unroll
            for (int q = 0; q < 2; q++) {
                int lrow = wm * 16 + (lane >> 2) + q * 8;
                s_lo[lrow * 2 + wn] = slo[q];
                s_hi[lrow * 2 + wn] = shi[q];
            }
        }
        __syncthreads();
        if (tid < 64) {
            int grow = m0 + tid;
            if (grow < M) {
                dlo[grow] = s_lo[tid * 2] + s_lo[tid * 2 + 1];
                dhi[grow] = s_hi[tid * 2] + s_hi[tid * 2 + 1];
            }
        }
    }
}

__global__ void __launch_bounds__(256, 2)
k_gemm0(const __nv_bfloat16* __restrict__ Ah, const __nv_bfloat16* __restrict__ Al,
        const __nv_bfloat16* __restrict__ Bh, const __nv_bfloat16* __restrict__ Bl,
        const float* __restrict__ bias, float* __restrict__ C, float* __restrict__ C2,
        int M, const float* __restrict__ awrow, float* __restrict__ dlo,
        float* __restrict__ dhi) {
    extern __shared__ char smem[];
    gemm_body<0>(Ah, Al, Bh, Bl, bias, 0.f, C, C2, M, blockIdx.x * 64,
                 awrow, dlo, dhi, smem);
}
template<int MODE>
__global__ void __launch_bounds__(256, 2)
k_gemm2(GP ga, GP gb, float beta, const float* __restrict__ awrow) {
    extern __shared__ char smem[];
    bool isA = blockIdx.x < (unsigned)ga.nblk;
    GP g = isA ? ga : gb;
    int m0 = (isA ? blockIdx.x : blockIdx.x - ga.nblk) * 64;
    gemm_body<MODE>(g.Ah, g.Al, g.Bh, g.Bl, nullptr, beta, g.C, nullptr,
                    g.M, m0, awrow, g.dlo, g.dhi, smem);
}

// ---------------- conversions ----------------
__global__ void k_cvt_rows(const float* __restrict__ src, __nv_bfloat16* __restrict__ hi,
                           __nv_bfloat16* __restrict__ lo, int n4) {
    int i = blockIdx.x * blockDim.x + threadIdx.x;
    if (i >= n4) return;
    float4 v = ((const float4*)src)[i];
    __nv_bfloat16 h0 = __float2bfloat16(v.x), h1 = __float2bfloat16(v.y);
    __nv_bfloat16 h2 = __float2bfloat16(v.z), h3 = __float2bfloat16(v.w);
    __nv_bfloat162 a, b;
    a.x = h0; a.y = h1; b.x = h2; b.y = h3;
    ((__nv_bfloat162*)hi)[2 * i] = a; ((__nv_bfloat162*)hi)[2 * i + 1] = b;
    a.x = __float2bfloat16(v.x - __bfloat162float(h0));
    a.y = __float2bfloat16(v.y - __bfloat162float(h1));
    b.x = __float2bfloat16(v.z - __bfloat162float(h2));
    b.y = __float2bfloat16(v.w - __bfloat162float(h3));
    ((__nv_bfloat162*)lo)[2 * i] = a; ((__nv_bfloat162*)lo)[2 * i + 1] = b;
}
__global__ void k_cvt_w2(const float* __restrict__ Wx, const float* __restrict__ We) {
    int i = blockIdx.x * blockDim.x + threadIdx.x;
    if (i >= 2 * D * D) return;
    const float* W = (i < D * D) ? Wx : We;
    __nv_bfloat16* hi = (i < D * D) ? g_wxh : g_weh;
    __nv_bfloat16* lo = (i < D * D) ? g_wxl : g_wel;
    int j = (i < D * D) ? i : i - D * D;
    int n = j >> 7, k = j & 127;
    float v = W[(size_t)k * D + n];
    __nv_bfloat16 h = __float2bfloat16(v);
    hi[j] = h;
    lo[j] = __float2bfloat16(v - __bfloat162float(h));
}
__global__ void k_cvt_w(const float* __restrict__ W, __nv_bfloat16* __restrict__ hi,
                        __nv_bfloat16* __restrict__ lo) {
    int i = blockIdx.x * blockDim.x + threadIdx.x;
    if (i >= D * D) return;
    int n = i >> 7, k = i & 127;
    float v = W[(size_t)k * D + n];
    __nv_bfloat16 h = __float2bfloat16(v);
    hi[i] = h;
    lo[i] = __float2bfloat16(v - __bfloat162float(h));
}

// ---------------- degrees / CSR setup (slimmed) ----------------
// node occurrence counts only (dV == ncnt, cnt[e] == eoff diff)
__global__ void k_count(const int* __restrict__ nodes) {
    int i = blockIdx.x * blockDim.x + threadIdx.x;
    if (i >= NZ) return;
    atomicAdd(&g_ncnt[nodes[i]], 1);
}
__global__ void k_eoff2(const int* __restrict__ edges) {
    int i = blockIdx.x * blockDim.x + threadIdx.x;
    if (i >= NZ) return;
    int e1 = edges[i];
    int e0 = (i == 0) ? -1 : edges[i - 1];
    for (int e = e0 + 1; e <= e1; e++) g_eoff[e] = i;
    if (i == NZ - 1)
        for (int e = e1 + 1; e <= NE; e++) g_eoff[e] = NZ;
}
// degE via warp-per-edge segment sum of ncnt[nodes[i]] (no atomics)
__global__ void k_degE(const int* __restrict__ nodes) {
    int t = blockIdx.x * blockDim.x + threadIdx.x;
    int w = t >> 5, lane = t & 31;
    if (w >= NE) return;
    int o0 = g_eoff[w], o1 = g_eoff[w + 1];
    float s = 0.f;
    for (int i = o0 + lane; i < o1; i += 32)
        s += (float)__ldg(g_ncnt + __ldg(nodes + i));
#pragma unroll
    for (int o = 16; o > 0; o >>= 1) s += __shfl_xor_sync(0xffffffffu, s, o);
    if (lane == 0) {
        float cnt = (float)(o1 - o0);
        float de = s / fmaxf(cnt, 1.f);
        g_degE[w] = (de > 0.f) ? rsqrtf(de) : 1.f;
    }
}
__global__ void k_degV() {
    int i = blockIdx.x * blockDim.x + threadIdx.x;
    if (i >= NN) return;
    int c = g_ncnt[i];
    g_degV[i] = (c > 0) ? rsqrtf((float)c) : 1.f;
}
__global__ void k_scan() {
    __shared__ int warpsum[32];
    __shared__ int s_run;
    const int tid = threadIdx.x, lane = tid & 31, wid = tid >> 5;
    if (tid == 0) s_run = 0;
    __syncthreads();
    for (int base = 0; base < NN; base += 1024) {
        int v = (base + tid < NN) ? g_ncnt[base + tid] : 0;
        int x = v;
#pragma unroll
        for (int o = 1; o < 32; o <<= 1) {
            int y = __shfl_up_sync(0xffffffffu, x, o);
            if (lane >= o) x += y;
        }
        if (lane == 31) warpsum[wid] = x;
        __syncthreads();
        if (wid == 0) {
            int s = warpsum[lane];
#pragma unroll
            for (int o = 1; o < 32; o <<= 1) {
                int y = __shfl_up_sync(0xffffffffu, s, o);
                if (lane >= o) s += y;
            }
            warpsum[lane] = s;
        }
        __syncthreads();
        int pref = (wid > 0) ? warpsum[wid - 1] : 0;
        int total = warpsum[31];
        int run = s_run;
        if (base + tid < NN) {
            g_noff[base + tid] = run + pref + x - v;
            g_ncur[base + tid] = run + pref + x - v;
        }
        __syncthreads();
        if (tid == 0) s_run += total;
        __syncthreads();
    }
    if (tid == 0) g_noff[NN] = NZ;
}
__global__ void k_scatter(const int* __restrict__ nodes, const int* __restrict__ edges,
                          const float* __restrict__ dn, const float* __restrict__ gn) {
    int i = blockIdx.x * blockDim.x + threadIdx.x;
    if (i >= NZ) return;
    int nd = nodes[i];
    int p = atomicAdd(&g_ncur[nd], 1);
    g_nedge[p] = edges[i];
    g_dnp[p] = dn[i];
    g_gnp[p] = gn[i];
}

// ---------------- rowdot (layer-0 e only) ----------------
__global__ void k_rowdot(const float* __restrict__ Mx, const float* __restrict__ vlo,
                         const float* __restrict__ vhi, float* __restrict__ olo,
                         float* __restrict__ ohi, int rows) {
    int t = blockIdx.x * blockDim.x + threadIdx.x;
    int w = t >> 5, lane = t & 31;
    if (w >= rows) return;
    float4 a  = ((const float4*)(Mx + (size_t)w * D))[lane];
    float4 l4 = ((const float4*)vlo)[lane];
    float4 h4 = ((const float4*)vhi)[lane];
    float slo = a.x * l4.x + a.y * l4.y + a.z * l4.z + a.w * l4.w;
    float shi = a.x * h4.x + a.y * h4.y + a.z * h4.z + a.w * h4.w;
#pragma unroll
    for (int o = 16; o > 0; o >>= 1) {
        slo += __shfl_xor_sync(0xffffffffu, slo, o);
        shi += __shfl_xor_sync(0xffffffffu, shi, o);
    }
    if (lane == 0) { olo[w] = slo; ohi[w] = shi; }
}

// ---------------- pass 1: fused attention, lane-distributed scalar math -------
__global__ void __launch_bounds__(256)
k_pass1(const int* __restrict__ nodes,
        const float* __restrict__ dv, const float* __restrict__ gv,
        const float* pab, const float* pwdw, const float* pwdb,
        const float* pwgw, const float* pwgb) {
    int t = blockIdx.x * blockDim.x + threadIdx.x;
    int w = t >> 5, lane = t & 31;
    float cst = *pab + *pwdb + *pwgb;
    float wdw = *pwdw, wgw = *pwgw;
    if (w < NE) {
        int o0 = g_eoff[w], o1 = g_eoff[w + 1];
        float base = g_se1[w] + cst;
        float4 acc = make_float4(0.f, 0.f, 0.f, 0.f);
        float4 acc2 = make_float4(0.f, 0.f, 0.f, 0.f);
        float den = 0.f;
        for (int i0 = o0; i0 < o1; i0 += 32) {
            int i = i0 + lane;
            int ndl = 0;
            float wexp = 0.f;
            if (i < o1) {
                ndl = __ldg(nodes + i);
                wexp = __expf(g_sx1[ndl] + base + dv[i] * wdw + gv[i] * wgw);
                g_sv[i] = wexp;
            }
            den += wexp;
            int cnt = min(32, o1 - i0);
            int k = 0;
            for (; k + 1 < cnt; k += 2) {
                float w0 = __shfl_sync(0xffffffffu, wexp, k);
                int  nd0 = __shfl_sync(0xffffffffu, ndl, k);
                float w1 = __shfl_sync(0xffffffffu, wexp, k + 1);
                int  nd1 = __shfl_sync(0xffffffffu, ndl, k + 1);
                float4 x0 = ((const float4*)(g_x + (size_t)nd0 * D))[lane];
                float4 x1 = ((const float4*)(g_x + (size_t)nd1 * D))[lane];
                acc.x = fmaf(x0.x, w0, acc.x); acc.y = fmaf(x0.y, w0, acc.y);
                acc.z = fmaf(x0.z, w0, acc.z); acc.w = fmaf(x0.w, w0, acc.w);
                acc2.x = fmaf(x1.x, w1, acc2.x); acc2.y = fmaf(x1.y, w1, acc2.y);
                acc2.z = fmaf(x1.z, w1, acc2.z); acc2.w = fmaf(x1.w, w1, acc2.w);
            }
            if (k < cnt) {
                float w0 = __shfl_sync(0xffffffffu, wexp, k);
                int  nd0 = __shfl_sync(0xffffffffu, ndl, k);
                float4 x0 = ((const float4*)(g_x + (size_t)nd0 * D))[lane];
                acc.x = fmaf(x0.x, w0, acc.x); acc.y = fmaf(x0.y, w0, acc.y);
                acc.z = fmaf(x0.z, w0, acc.z); acc.w = fmaf(x0.w, w0, acc.w);
            }
        }
#pragma unroll
        for (int o = 16; o > 0; o >>= 1) den += __shfl_xor_sync(0xffffffffu, den, o);
        if (lane == 0) g_denE[w] = den;
        float s = (o1 > o0) ? g_degE[w] / den : 0.f;
        ((float4*)(g_Xe1 + (size_t)w * D))[lane] =
            make_float4((acc.x + acc2.x) * s, (acc.y + acc2.y) * s,
                        (acc.z + acc2.z) * s, (acc.w + acc2.w) * s);
    } else {
        w -= NE;
        if (w >= NN) return;
        int o0 = g_noff[w], o1 = g_noff[w + 1];
        float base = g_sx2[w] + cst;
        float4 acc = make_float4(0.f, 0.f, 0.f, 0.f);
        float4 acc2 = make_float4(0.f, 0.f, 0.f, 0.f);
        float den = 0.f;
        for (int j0 = o0; j0 < o1; j0 += 32) {
            int j = j0 + lane;
            int edl = 0;
            float wexp = 0.f;
            if (j < o1) {
                edl = __ldg(g_nedge + j);
                wexp = __expf(g_se2[edl] + base + g_dnp[j] * wdw + g_gnp[j] * wgw);
                g_snp[j] = wexp;
            }
            den += wexp;
            int cnt = min(32, o1 - j0);
            int k = 0;
            for (; k + 1 < cnt; k += 2) {
                float w0 = __shfl_sync(0xffffffffu, wexp, k);
                int  ed0 = __shfl_sync(0xffffffffu, edl, k);
                float w1 = __shfl_sync(0xffffffffu, wexp, k + 1);
                int  ed1 = __shfl_sync(0xffffffffu, edl, k + 1);
                float4 e0 = ((const float4*)(g_e + (size_t)ed0 * D))[lane];
                float4 e1 = ((const float4*)(g_e + (size_t)ed1 * D))[lane];
                acc.x = fmaf(e0.x, w0, acc.x); acc.y = fmaf(e0.y, w0, acc.y);
                acc.z = fmaf(e0.z, w0, acc.z); acc.w = fmaf(e0.w, w0, acc.w);
                acc2.x = fmaf(e1.x, w1, acc2.x); acc2.y = fmaf(e1.y, w1, acc2.y);
                acc2.z = fmaf(e1.z, w1, acc2.z); acc2.w = fmaf(e1.w, w1, acc2.w);
            }
            if (k < cnt) {
                float w0 = __shfl_sync(0xffffffffu, wexp, k);
                int  ed0 = __shfl_sync(0xffffffffu, edl, k);
                float4 e0 = ((const float4*)(g_e + (size_t)ed0 * D))[lane];
                acc.x = fmaf(e0.x, w0, acc.x); acc.y = fmaf(e0.y, w0, acc.y);
                acc.z = fmaf(e0.z, w0, acc.z); acc.w = fmaf(e0.w, w0, acc.w);
            }
        }
#pragma unroll
        for (int o = 16; o > 0; o >>= 1) den += __shfl_xor_sync(0xffffffffu, den, o);
        if (lane == 0) g_denN[w] = den;
        float s = (o1 > o0) ? g_degV[w] / den : 0.f;
        ((float4*)(g_Xv2 + (size_t)w * D))[lane] =
            make_float4((acc.x + acc2.x) * s, (acc.y + acc2.y) * s,
                        (acc.z + acc2.z) * s, (acc.w + acc2.w) * s);
    }
}

// ---------------- bf16 split helper ----------------
__device__ __forceinline__ void split_store4(__nv_bfloat16* hi, __nv_bfloat16* lo,
                                             int i, float4 r) {
    __nv_bfloat16 h0 = __float2bfloat16(r.x), h1 = __float2bfloat16(r.y);
    __nv_bfloat16 h2 = __float2bfloat16(r.z), h3 = __float2bfloat16(r.w);
    __nv_bfloat162 a, b;
    a.x = h0; a.y = h1; b.x = h2; b.y = h3;
    ((__nv_bfloat162*)hi)[2 * i] = a; ((__nv_bfloat162*)hi)[2 * i + 1] = b;
    a.x = __float2bfloat16(r.x - __bfloat162float(h0));
    a.y = __float2bfloat16(r.y - __bfloat162float(h1));
    b.x = __float2bfloat16(r.z - __bfloat162float(h2));
    b.y = __float2bfloat16(r.w - __bfloat162float(h3));
    ((__nv_bfloat162*)lo)[2 * i] = a; ((__nv_bfloat162*)lo)[2 * i + 1] = b;
}

// ---------------- pass 2 + fused mixes + bf16 split ---------------------------
__global__ void __launch_bounds__(256)
k_pass2(const int* __restrict__ nodes, const float* __restrict__ e0) {
    int t = blockIdx.x * blockDim.x + threadIdx.x;
    int w = t >> 5, lane = t & 31;
    if (w < NE) {
        int o0 = g_eoff[w], o1 = g_eoff[w + 1];
        float4 acc = make_float4(0.f, 0.f, 0.f, 0.f);
        float4 acc2 = make_float4(0.f, 0.f, 0.f, 0.f);
        int i = o0;
        for (; i + 3 < o1; i += 4) {
            int nd0 = __ldg(nodes + i),     nd1 = __ldg(nodes + i + 1);
            int nd2 = __ldg(nodes + i + 2), nd3 = __ldg(nodes + i + 3);
            float w0 = g_sv[i], w1 = g_sv[i + 1], w2 = g_sv[i + 2], w3 = g_sv[i + 3];
            float4 x0 = ((const float4*)(g_Xv2 + (size_t)nd0 * D))[lane];
            float4 x1 = ((const float4*)(g_Xv2 + (size_t)nd1 * D))[lane];
            float4 x2 = ((const float4*)(g_Xv2 + (size_t)nd2 * D))[lane];
            float4 x3 = ((const float4*)(g_Xv2 + (size_t)nd3 * D))[lane];
            acc.x = fmaf(x0.x, w0, acc.x); acc.y = fmaf(x0.y, w0, acc.y);
            acc.z = fmaf(x0.z, w0, acc.z); acc.w = fmaf(x0.w, w0, acc.w);
            acc2.x = fmaf(x1.x, w1, acc2.x); acc2.y = fmaf(x1.y, w1, acc2.y);
            acc2.z = fmaf(x1.z, w1, acc2.z); acc2.w = fmaf(x1.w, w1, acc2.w);
            acc.x = fmaf(x2.x, w2, acc.x); acc.y = fmaf(x2.y, w2, acc.y);
            acc.z = fmaf(x2.z, w2, acc.z); acc.w = fmaf(x2.w, w2, acc.w);
            acc2.x = fmaf(x3.x, w3, acc2.x); acc2.y = fmaf(x3.y, w3, acc2.y);
            acc2.z = fmaf(x3.z, w3, acc2.z); acc2.w = fmaf(x3.w, w3, acc2.w);
        }
        for (; i < o1; i++) {
            int nd = __ldg(nodes + i);
            float wv = g_sv[i];
            float4 vr = ((const float4*)(g_Xv2 + (size_t)nd * D))[lane];
            acc.x = fmaf(vr.x, wv, acc.x); acc.y = fmaf(vr.y, wv, acc.y);
            acc.z = fmaf(vr.z, wv, acc.z); acc.w = fmaf(vr.w, wv, acc.w);
        }
        float s = (o1 > o0) ? 1.f / g_denE[w] : 0.f;
        float sc = 0.45f * g_degE[w] * s;
        float4 xe1 = ((const float4*)(g_Xe1 + (size_t)w * D))[lane];
        float4 ev  = ((const float4*)(e0 + (size_t)w * D))[lane];
        float4 r;
        r.x = sc * (acc.x + acc2.x) + 0.45f * xe1.x + 0.1f * ev.x;
        r.y = sc * (acc.y + acc2.y) + 0.45f * xe1.y + 0.1f * ev.y;
        r.z = sc * (acc.z + acc2.z) + 0.45f * xe1.z + 0.1f * ev.z;
        r.w = sc * (acc.w + acc2.w) + 0.45f * xe1.w + 0.1f * ev.w;
        split_store4(g_ebh, g_ebl, w * 32 + lane, r);
    } else {
        w -= NE;
        if (w >= NN) return;
        int o0 = g_noff[w], o1 = g_noff[w + 1];
        float4 acc = make_float4(0.f, 0.f, 0.f, 0.f);
        float4 acc2 = make_float4(0.f, 0.f, 0.f, 0.f);
        int j = o0;
        for (; j + 1 < o1; j += 2) {
            int ed0 = __ldg(g_nedge + j), ed1 = __ldg(g_nedge + j + 1);
            float w0 = g_snp[j], w1 = g_snp[j + 1];
            float4 e0r = ((const float4*)(g_Xe1 + (size_t)ed0 * D))[lane];
            float4 e1r = ((const float4*)(g_Xe1 + (size_t)ed1 * D))[lane];
            acc.x = fmaf(e0r.x, w0, acc.x); acc.y = fmaf(e0r.y, w0, acc.y);
            acc.z = fmaf(e0r.z, w0, acc.z); acc.w = fmaf(e0r.w, w0, acc.w);
            acc2.x = fmaf(e1r.x, w1, acc2.x); acc2.y = fmaf(e1r.y, w1, acc2.y);
            acc2.z = fmaf(e1r.z, w1, acc2.z); acc2.w = fmaf(e1r.w, w1, acc2.w);
        }
        if (j < o1) {
            int ed = __ldg(g_nedge + j);
            float wn = g_snp[j];
            float4 xr = ((const float4*)(g_Xe1 + (size_t)ed * D))[lane];
            acc.x = fmaf(xr.x, wn, acc.x); acc.y = fmaf(xr.y, wn, acc.y);
            acc.z = fmaf(xr.z, wn, acc.z); acc.w = fmaf(xr.w, wn, acc.w);
        }
        float s = (o1 > o0) ? 1.f / g_denN[w] : 0.f;
        float sc = 0.45f * g_degV[w] * s;
        float4 v2 = ((const float4*)(g_Xv2 + (size_t)w * D))[lane];
        float4 x0 = ((const float4*)(g_x0 + (size_t)w * D))[lane];
        float4 r;
        r.x = sc * (acc.x + acc2.x) + 0.45f * v2.x + 0.1f * x0.x;
        r.y = sc * (acc.y + acc2.y) + 0.45f * v2.y + 0.1f * x0.y;
        r.z = sc * (acc.z + acc2.z) + 0.45f * v2.z + 0.1f * x0.z;
        r.w = sc * (acc.w + acc2.w) + 0.45f * v2.w + 0.1f * x0.w;
        split_store4(g_ah, g_al, w * 32 + lane, r);
    }
}

// ---------------- launch ----------------
extern "C" void kernel_launch(void* const* d_in, const int* in_sizes, int n_in,
                              void* d_out, int out_size) {
    const float* x_in = (const float*)d_in[0];
    const float* e_in = (const float*)d_in[1];
    const int*   hei  = (const int*)d_in[2];
    const int*   nodes = hei;
    const int*   edges = hei + NZ;
    const float* dv2e = (const float*)d_in[3];
    const float* gv2e = (const float*)d_in[4];
    const float* de2v = (const float*)d_in[5];
    const float* ge2v = (const float*)d_in[6];
    const float* W0   = (const float*)d_in[7];
    const float* b0   = (const float*)d_in[8];
    const float* Wn   = (const float*)d_in[9];
    const float* We   = (const float*)d_in[10];
    const float* aw   = (const float*)d_in[11];
    const float* ab   = (const float*)d_in[12];
    const float* wdw  = (const float*)d_in[13];
    const float* wdb  = (const float*)d_in[14];
    const float* wgw  = (const float*)d_in[15];
    const float* wgb  = (const float*)d_in[16];
    float* out = (float*)d_out;

    cudaFuncSetAttribute(k_gemm0, cudaFuncAttributeMaxDynamicSharedMemorySize, SMEM_MMA);
    cudaFuncSetAttribute(k_gemm2<1>, cudaFuncAttributeMaxDynamicSharedMemorySize, SMEM_MMA);
    cudaFuncSetAttribute(k_gemm2<2>, cudaFuncAttributeMaxDynamicSharedMemorySize, SMEM_MMA);

    void *pncnt;
    void *px, *px0, *pe, *psx1, *psx2, *pse1, *pse2;
    void *pah, *pal, *pebh, *pebl, *pwxh, *pwxl, *pweh, *pwel;
    cudaGetSymbolAddress(&pncnt, g_ncnt);
    cudaGetSymbolAddress(&px, g_x);       cudaGetSymbolAddress(&px0, g_x0);
    cudaGetSymbolAddress(&pe, g_e);
    cudaGetSymbolAddress(&psx1, g_sx1);   cudaGetSymbolAddress(&psx2, g_sx2);
    cudaGetSymbolAddress(&pse1, g_se1);   cudaGetSymbolAddress(&pse2, g_se2);
    cudaGetSymbolAddress(&pah, g_ah);     cudaGetSymbolAddress(&pal, g_al);
    cudaGetSymbolAddress(&pebh, g_ebh);   cudaGetSymbolAddress(&pebl, g_ebl);
    cudaGetSymbolAddress(&pwxh, g_wxh);   cudaGetSymbolAddress(&pwxl, g_wxl);
    cudaGetSymbolAddress(&pweh, g_weh);   cudaGetSymbolAddress(&pwel, g_wel);

    const int B = 256;
    const int gNZ   = (NZ + B - 1) / B;
    const int gNN   = (NN + B - 1) / B;
    const int gEW   = (NE * 32 + B - 1) / B;
    const int gPASS = ((NE + NN) * 32 + B - 1) / B;
    const int gXT   = (NN + 63) / 64;
    const int gET   = (NE + 63) / 64;

    // ---- one-time setup (slimmed: 1 memset, 1 atomic/nnz) ----
    cudaMemsetAsync(pncnt, 0, NN * 4, 0);
    k_count<<<gNZ, B>>>(nodes);
    k_eoff2<<<gNZ, B>>>(edges);
    k_degE<<<gEW, B>>>(nodes);
    k_degV<<<gNN, B>>>();
    k_scan<<<1, 1024>>>();
    k_scatter<<<gNZ, B>>>(nodes, edges, de2v, ge2v);

    k_cvt_rows<<<(NN * D / 4 + B - 1) / B, B>>>(x_in, (__nv_bfloat16*)pah, (__nv_bfloat16*)pal,
                                                NN * D / 4);
    k_cvt_w<<<(D * D + B - 1) / B, B>>>(W0, (__nv_bfloat16*)pwxh, (__nv_bfloat16*)pwxl);
    k_gemm0<<<gXT, 256, SMEM_MMA>>>((__nv_bfloat16*)pah, (__nv_bfloat16*)pal,
                                    (__nv_bfloat16*)pwxh, (__nv_bfloat16*)pwxl,
                                    b0, (float*)px, (float*)px0, NN,
                                    aw, (float*)psx1, (float*)psx2);
    cudaMemcpyAsync(pe, e_in, (size_t)NE * D * 4, cudaMemcpyDeviceToDevice, 0);
    k_rowdot<<<(NE * 32 + B - 1) / B, B>>>(e_in, aw, aw + D, (float*)pse2, (float*)pse1, NE);

    bool both = (out_size >= (NN + NE) * D);

    for (int l = 0; l < NL; l++) {
        float beta = logf(0.5f / (float)(l + 1) + 1.f);

        k_pass1<<<gPASS, B>>>(nodes, dv2e, gv2e,
                              ab + l, wdw + l, wdb + l, wgw + l, wgb + l);
        k_pass2<<<gPASS, B>>>(nodes, e_in);

        k_cvt_w2<<<(2 * D * D + B - 1) / B, B>>>(Wn + (size_t)l * D * D,
                                                 We + (size_t)l * D * D);

        GP gx, ge;
        gx.Ah = (__nv_bfloat16*)pah; gx.Al = (__nv_bfloat16*)pal;
        gx.Bh = (__nv_bfloat16*)pwxh; gx.Bl = (__nv_bfloat16*)pwxl;
        gx.M = NN; gx.nblk = gXT;
        gx.dlo = (float*)psx1; gx.dhi = (float*)psx2;
        ge.Ah = (__nv_bfloat16*)pebh; ge.Al = (__nv_bfloat16*)pebl;
        ge.Bh = (__nv_bfloat16*)pweh; ge.Bl = (__nv_bfloat16*)pwel;
        ge.M = NE; ge.nblk = gET;
        ge.dlo = (float*)pse2; ge.dhi = (float*)pse1;

        if (l < NL - 1) {
            gx.C = (float*)px;
            ge.C = (float*)pe;
            const float* awn = aw + (size_t)(l + 1) * 2 * D;
            k_gemm2<1><<<gXT + gET, 256, SMEM_MMA>>>(gx, ge, beta, awn);
        } else {
            gx.C = out;
            ge.C = both ? out + (size_t)NN * D : (float*)pe;
            k_gemm2<2><<<gXT + gET, 256, SMEM_MMA>>>(gx, ge, beta, nullptr);
        }
    }
}

// round 15
// speedup vs baseline: 1.0673x; 1.0129x over previous
#include <cuda_runtime.h>
#include <cuda_bf16.h>
#include <math.h>
#include <stdint.h>

#define NN 100000
#define NE 20000
#define NZ 500000
#define D  128
#define NL 4

// ---------------- scratch ----------------
__device__ float g_degV[NN], g_denN[NN], g_sx1[NN], g_sx2[NN];
__device__ float g_degE[NE], g_denE[NE], g_se1[NE], g_se2[NE];
__device__ int   g_eoff[NE + 1];
__device__ int   g_ncnt[NN], g_noff[NN + 1], g_ncur[NN];
__device__ int   g_nedge[NZ];
__device__ float g_dnp[NZ], g_gnp[NZ];
__device__ float g_x [NN * D];
__device__ float g_x0[NN * D];
__device__ float g_Xv2[NN * D];
__device__ float g_e [NE * D];
__device__ float g_Xe1[NE * D];
__device__ float g_sv[NZ], g_snp[NZ];
__device__ __nv_bfloat16 g_ah[NN * D], g_al[NN * D];
__device__ __nv_bfloat16 g_ebh[NE * D], g_ebl[NE * D];
// all layer weights, pre-converted once: [0]=W0, then Wn[l] / We[l]
__device__ __nv_bfloat16 g_w0h[D * D], g_w0l[D * D];
__device__ __nv_bfloat16 g_wnh[NL * D * D], g_wnl[NL * D * D];
__device__ __nv_bfloat16 g_weh[NL * D * D], g_wel[NL * D * D];

// ---------------- mma / cp.async helpers (portable sm_80+ PTX) ----------------
__device__ __forceinline__ uint32_t s2u(const void* p) {
    uint32_t a;
    asm("{ .reg .u64 t; cvta.to.shared.u64 t, %1; cvt.u32.u64 %0, t; }" : "=r"(a) : "l"(p));
    return a;
}
__device__ __forceinline__ void ldsm4(uint32_t& r0, uint32_t& r1, uint32_t& r2, uint32_t& r3,
                                      uint32_t addr) {
    asm volatile("ldmatrix.sync.aligned.m8n8.x4.shared.b16 {%0,%1,%2,%3}, [%4];"
                 : "=r"(r0), "=r"(r1), "=r"(r2), "=r"(r3) : "r"(addr));
}
__device__ __forceinline__ void mma_bf16(float* c, const uint32_t* a, const uint32_t* b) {
    asm volatile("mma.sync.aligned.m16n8k16.row.col.f32.bf16.bf16.f32 "
                 "{%0,%1,%2,%3}, {%4,%5,%6,%7}, {%8,%9}, {%0,%1,%2,%3};"
                 : "+f"(c[0]), "+f"(c[1]), "+f"(c[2]), "+f"(c[3])
                 : "r"(a[0]), "r"(a[1]), "r"(a[2]), "r"(a[3]), "r"(b[0]), "r"(b[1]));
}
__device__ __forceinline__ void cpa16(uint32_t dst, const void* src, bool pred) {
    int sz = pred ? 16 : 0;
    asm volatile("cp.async.cg.shared.global [%0], [%1], 16, %2;"
                 :: "r"(dst), "l"(src), "r"(sz) : "memory");
}
__device__ __forceinline__ void cp_commit() {
    asm volatile("cp.async.commit_group;" ::: "memory");
}
template<int N>
__device__ __forceinline__ void cp_wait() {
    asm volatile("cp.async.wait_group %0;" :: "n"(N) : "memory");
}

// smem tiles: A = 64 rows, B = 128 rows, stride 136 bf16
#define TSTRIDE 136
#define ATILEB  (64 * TSTRIDE * 2)
#define BTILEB  (128 * TSTRIDE * 2)
#define SM_AH   0
#define SM_AL   (ATILEB)
#define SM_BH   (2 * ATILEB)
#define SM_BL   (2 * ATILEB + BTILEB)
#define SM_AW   (2 * ATILEB + 2 * BTILEB)
#define SM_BIAS (SM_AW + 1024)
#define SM_DLO  (SM_BIAS + 512)
#define SM_DHI  (SM_DLO + 512)
#define SMEM_MMA (SM_DHI + 512)

__device__ __forceinline__ void load_tileA(const __nv_bfloat16* __restrict__ g,
                                           int row0, int Mlim, uint32_t sb, int soff) {
    for (int idx = threadIdx.x; idx < 1024; idx += 256) {
        int r = idx >> 4;
        int c8 = (idx & 15) << 3;
        int gr = row0 + r;
        bool ok = gr < Mlim;
        int gs = ok ? gr : 0;
        cpa16(sb + soff + (uint32_t)((r * TSTRIDE + c8) * 2), g + (size_t)gs * D + c8, ok);
    }
}
__device__ __forceinline__ void load_tileB(const __nv_bfloat16* __restrict__ g,
                                           uint32_t sb, int soff) {
    for (int idx = threadIdx.x; idx < 2048; idx += 256) {
        int r = idx >> 4;
        int c8 = (idx & 15) << 3;
        cpa16(sb + soff + (uint32_t)((r * TSTRIDE + c8) * 2), g + (size_t)r * D + c8, true);
    }
}

struct GP {
    const __nv_bfloat16 *Ah, *Al, *Bh, *Bl;
    float* C;
    float* dlo;
    float* dhi;
    int M;
    int nblk;
};

// ---------------- GEMM core (bf16x3, fp32 acc, 64-row tile) --------------------
template<int MODE>
__device__ __forceinline__ void gemm_body(
    const __nv_bfloat16* __restrict__ Ah, const __nv_bfloat16* __restrict__ Al,
    const __nv_bfloat16* __restrict__ Bh, const __nv_bfloat16* __restrict__ Bl,
    const float* __restrict__ bias, float beta,
    float* __restrict__ C, float* __restrict__ C2, int M, int m0,
    const float* __restrict__ awrow, float* __restrict__ dlo, float* __restrict__ dhi,
    char* smem) {
    const int tid = threadIdx.x, lane = tid & 31, wid = tid >> 5;
    const int wm = wid >> 1, wn = wid & 1;
    uint32_t sb = s2u(smem);

    load_tileA(Ah, m0, M, sb, SM_AH);
    load_tileB(Bh, sb, SM_BH);
    cp_commit();
    load_tileA(Al, m0, M, sb, SM_AL);
    load_tileB(Bl, sb, SM_BL);
    cp_commit();

    float* s_aw = (float*)(smem + SM_AW);
    float* s_bias = (float*)(smem + SM_BIAS);
    float* s_lo = (float*)(smem + SM_DLO);
    float* s_hi = (float*)(smem + SM_DHI);
    if (MODE != 2) { if (tid < 256) s_aw[tid] = awrow[tid]; }
    if (MODE == 0) { if (tid < 128) s_bias[tid] = bias[tid]; }

    cp_wait<1>();
    __syncthreads();

    float acc[8][4];
#pragma unroll
    for (int nt = 0; nt < 8; nt++)
#pragma unroll
        for (int q = 0; q < 4; q++) acc[nt][q] = 0.f;

    const int a_row16 = (lane & 7) + (((lane >> 3) & 1) << 3);
    const int a_col   = ((lane >> 4) & 1) << 3;
    const int b_nin   = (lane & 7) + (((lane >> 4) & 1) << 3);
    const int b_col   = ((lane >> 3) & 1) << 3;

    const int apass[3] = {SM_AH, SM_AH, SM_AL};
    const int bpass[3] = {SM_BH, SM_BL, SM_BH};

#pragma unroll
    for (int p = 0; p < 3; p++) {
        if (p == 1) { cp_wait<0>(); __syncthreads(); }
        uint32_t aoff = sb + apass[p];
        uint32_t boff = sb + bpass[p];
#pragma unroll
        for (int ks = 0; ks < 8; ks++) {
            uint32_t a[4];
            {
                uint32_t addr = aoff + (uint32_t)(((wm * 16 + a_row16) * TSTRIDE
                                                  + ks * 16 + a_col) * 2);
                ldsm4(a[0], a[1], a[2], a[3], addr);
            }
            uint32_t b[8][2];
#pragma unroll
            for (int ntp = 0; ntp < 4; ntp++) {
                uint32_t addr = boff + (uint32_t)(((wn * 64 + ntp * 16 + b_nin) * TSTRIDE
                                                  + ks * 16 + b_col) * 2);
                ldsm4(b[2 * ntp][0], b[2 * ntp][1], b[2 * ntp + 1][0], b[2 * ntp + 1][1], addr);
            }
#pragma unroll
            for (int nt = 0; nt < 8; nt++)
                mma_bf16(acc[nt], a, b[nt]);
        }
    }

    const float ob = 1.f - beta;
    const __nv_bfloat162* sAh2 = (const __nv_bfloat162*)(smem + SM_AH);
    const __nv_bfloat162* sAl2 = (const __nv_bfloat162*)(smem + SM_AL);
    float slo[2] = {0.f, 0.f}, shi[2] = {0.f, 0.f};
#pragma unroll
    for (int nt = 0; nt < 8; nt++) {
        int col = wn * 64 + nt * 8 + (lane & 3) * 2;
        int lr0 = wm * 16 + (lane >> 2);
        int lr1 = lr0 + 8;
        int r0 = m0 + lr0;
        int r1 = m0 + lr1;
        float2 v0 = make_float2(acc[nt][0], acc[nt][1]);
        float2 v1 = make_float2(acc[nt][2], acc[nt][3]);
        if (MODE == 0) {
            float2 bb = *(const float2*)(s_bias + col);
            v0.x = fmaxf(v0.x + bb.x, 0.f); v0.y = fmaxf(v0.y + bb.y, 0.f);
            v1.x = fmaxf(v1.x + bb.x, 0.f); v1.y = fmaxf(v1.y + bb.y, 0.f);
            if (r0 < M) { *(float2*)(C + (size_t)r0 * D + col) = v0;
                          *(float2*)(C2 + (size_t)r0 * D + col) = v0; }
            if (r1 < M) { *(float2*)(C + (size_t)r1 * D + col) = v1;
                          *(float2*)(C2 + (size_t)r1 * D + col) = v1; }
        } else {
            int idx0 = (lr0 * TSTRIDE + col) >> 1;
            int idx1 = (lr1 * TSTRIDE + col) >> 1;
            __nv_bfloat162 h0 = sAh2[idx0], l0 = sAl2[idx0];
            __nv_bfloat162 h1 = sAh2[idx1], l1 = sAl2[idx1];
            float2 a0 = make_float2(__bfloat162float(h0.x) + __bfloat162float(l0.x),
                                    __bfloat162float(h0.y) + __bfloat162float(l0.y));
            float2 a1 = make_float2(__bfloat162float(h1.x) + __bfloat162float(l1.x),
                                    __bfloat162float(h1.y) + __bfloat162float(l1.y));
            v0.x = ob * a0.x + beta * v0.x; v0.y = ob * a0.y + beta * v0.y;
            v1.x = ob * a1.x + beta * v1.x; v1.y = ob * a1.y + beta * v1.y;
            if (MODE == 1) {
                v0.x = fmaxf(v0.x, 0.f); v0.y = fmaxf(v0.y, 0.f);
                v1.x = fmaxf(v1.x, 0.f); v1.y = fmaxf(v1.y, 0.f);
            }
            if (r0 < M) *(float2*)(C + (size_t)r0 * D + col) = v0;
            if (r1 < M) *(float2*)(C + (size_t)r1 * D + col) = v1;
        }
        if (MODE != 2) {
            float2 wl = *(const float2*)(s_aw + col);
            float2 wh = *(const float2*)(s_aw + 128 + col);
            slo[0] += v0.x * wl.x + v0.y * wl.y;
            shi[0] += v0.x * wh.x + v0.y * wh.y;
            slo[1] += v1.x * wl.x + v1.y * wl.y;
            shi[1] += v1.x * wh.x + v1.y * wh.y;
        }
    }
    if (MODE != 2) {
#pragma unroll
        for (int q = 0; q < 2; q++) {
            slo[q] += __shfl_xor_sync(0xffffffffu, slo[q], 1);
            slo[q] += __shfl_xor_sync(0xffffffffu, slo[q], 2);
            shi[q] += __shfl_xor_sync(0xffffffffu, shi[q], 1);
            shi[q] += __shfl_xor_sync(0xffffffffu, shi[q], 2);
        }
        if ((lane & 3) == 0) {
#pragma unroll
            for (int q = 0; q < 2; q++) {
                int lrow = wm * 16 + (lane >> 2) + q * 8;
                s_lo[lrow * 2 + wn] = slo[q];
                s_hi[lrow * 2 + wn] = shi[q];
            }
        }
        __syncthreads();
        if (tid < 64) {
            int grow = m0 + tid;
            if (grow < M) {
                dlo[grow] = s_lo[tid * 2] + s_lo[tid * 2 + 1];
                dhi[grow] = s_hi[tid * 2] + s_hi[tid * 2 + 1];
            }
        }
    }
}

__global__ void __launch_bounds__(256, 2)
k_gemm0(const __nv_bfloat16* __restrict__ Ah, const __nv_bfloat16* __restrict__ Al,
        const __nv_bfloat16* __restrict__ Bh, const __nv_bfloat16* __restrict__ Bl,
        const float* __restrict__ bias, float* __restrict__ C, float* __restrict__ C2,
        int M, const float* __restrict__ awrow, float* __restrict__ dlo,
        float* __restrict__ dhi) {
    extern __shared__ char smem[];
    gemm_body<0>(Ah, Al, Bh, Bl, bias, 0.f, C, C2, M, blockIdx.x * 64,
                 awrow, dlo, dhi, smem);
}
template<int MODE>
__global__ void __launch_bounds__(256, 2)
k_gemm2(GP ga, GP gb, float beta, const float* __restrict__ awrow) {
    extern __shared__ char smem[];
    bool isA = blockIdx.x < (unsigned)ga.nblk;
    GP g = isA ? ga : gb;
    int m0 = (isA ? blockIdx.x : blockIdx.x - ga.nblk) * 64;
    gemm_body<MODE>(g.Ah, g.Al, g.Bh, g.Bl, nullptr, beta, g.C, nullptr,
                    g.M, m0, awrow, g.dlo, g.dhi, smem);
}

// ---------------- conversions ----------------
__global__ void k_cvt_rows(const float* __restrict__ src, __nv_bfloat16* __restrict__ hi,
                           __nv_bfloat16* __restrict__ lo, int n4) {
    int i = blockIdx.x * blockDim.x + threadIdx.x;
    if (i >= n4) return;
    float4 v = ((const float4*)src)[i];
    __nv_bfloat16 h0 = __float2bfloat16(v.x), h1 = __float2bfloat16(v.y);
    __nv_bfloat16 h2 = __float2bfloat16(v.z), h3 = __float2bfloat16(v.w);
    __nv_bfloat162 a, b;
    a.x = h0; a.y = h1; b.x = h2; b.y = h3;
    ((__nv_bfloat162*)hi)[2 * i] = a; ((__nv_bfloat162*)hi)[2 * i + 1] = b;
    a.x = __float2bfloat16(v.x - __bfloat162float(h0));
    a.y = __float2bfloat16(v.y - __bfloat162float(h1));
    b.x = __float2bfloat16(v.z - __bfloat162float(h2));
    b.y = __float2bfloat16(v.w - __bfloat162float(h3));
    ((__nv_bfloat162*)lo)[2 * i] = a; ((__nv_bfloat162*)lo)[2 * i + 1] = b;
}
// one-shot: convert W0 + all Wn/We layers (transposed, split hi/lo)
__global__ void k_cvt_allw(const float* __restrict__ W0,
                           const float* __restrict__ Wn, const float* __restrict__ We) {
    int i = blockIdx.x * blockDim.x + threadIdx.x;
    int total = (1 + 2 * NL) * D * D;
    if (i >= total) return;
    int m = i / (D * D);          // 0 = W0, 1..NL = Wn, NL+1..2NL = We
    int j = i - m * (D * D);
    int n = j >> 7, k = j & 127;
    const float* W;
    __nv_bfloat16 *hi, *lo;
    if (m == 0) { W = W0; hi = g_w0h; lo = g_w0l; }
    else if (m <= NL) {
        int l = m - 1;
        W = Wn + (size_t)l * D * D; hi = g_wnh + (size_t)l * D * D; lo = g_wnl + (size_t)l * D * D;
    } else {
        int l = m - NL - 1;
        W = We + (size_t)l * D * D; hi = g_weh + (size_t)l * D * D; lo = g_wel + (size_t)l * D * D;
    }
    float v = W[(size_t)k * D + n];
    __nv_bfloat16 h = __float2bfloat16(v);
    hi[j] = h;
    lo[j] = __float2bfloat16(v - __bfloat162float(h));
}

// ---------------- degrees / CSR setup (slimmed) ----------------
__global__ void k_count(const int* __restrict__ nodes) {
    int i = blockIdx.x * blockDim.x + threadIdx.x;
    if (i >= NZ) return;
    atomicAdd(&g_ncnt[nodes[i]], 1);
}
__global__ void k_eoff2(const int* __restrict__ edges) {
    int i = blockIdx.x * blockDim.x + threadIdx.x;
    if (i >= NZ) return;
    int e1 = edges[i];
    int e0 = (i == 0) ? -1 : edges[i - 1];
    for (int e = e0 + 1; e <= e1; e++) g_eoff[e] = i;
    if (i == NZ - 1)
        for (int e = e1 + 1; e <= NE; e++) g_eoff[e] = NZ;
}
__global__ void k_degE(const int* __restrict__ nodes) {
    int t = blockIdx.x * blockDim.x + threadIdx.x;
    int w = t >> 5, lane = t & 31;
    if (w >= NE) return;
    int o0 = g_eoff[w], o1 = g_eoff[w + 1];
    float s = 0.f;
    for (int i = o0 + lane; i < o1; i += 32)
        s += (float)__ldg(g_ncnt + __ldg(nodes + i));
#pragma unroll
    for (int o = 16; o > 0; o >>= 1) s += __shfl_xor_sync(0xffffffffu, s, o);
    if (lane == 0) {
        float cnt = (float)(o1 - o0);
        float de = s / fmaxf(cnt, 1.f);
        g_degE[w] = (de > 0.f) ? rsqrtf(de) : 1.f;
    }
}
// scan with fused degV computation
__global__ void k_scan() {
    __shared__ int warpsum[32];
    __shared__ int s_run;
    const int tid = threadIdx.x, lane = tid & 31, wid = tid >> 5;
    if (tid == 0) s_run = 0;
    __syncthreads();
    for (int base = 0; base < NN; base += 1024) {
        int v = (base + tid < NN) ? g_ncnt[base + tid] : 0;
        if (base + tid < NN)
            g_degV[base + tid] = (v > 0) ? rsqrtf((float)v) : 1.f;
        int x = v;
#pragma unroll
        for (int o = 1; o < 32; o <<= 1) {
            int y = __shfl_up_sync(0xffffffffu, x, o);
            if (lane >= o) x += y;
        }
        if (lane == 31) warpsum[wid] = x;
        __syncthreads();
        if (wid == 0) {
            int s = warpsum[lane];
#pragma unroll
            for (int o = 1; o < 32; o <<= 1) {
                int y = __shfl_up_sync(0xffffffffu, s, o);
                if (lane >= o) s += y;
            }
            warpsum[lane] = s;
        }
        __syncthreads();
        int pref = (wid > 0) ? warpsum[wid - 1] : 0;
        int total = warpsum[31];
        int run = s_run;
        if (base + tid < NN) {
            g_noff[base + tid] = run + pref + x - v;
            g_ncur[base + tid] = run + pref + x - v;
        }
        __syncthreads();
        if (tid == 0) s_run += total;
        __syncthreads();
    }
    if (tid == 0) g_noff[NN] = NZ;
}
__global__ void k_scatter(const int* __restrict__ nodes, const int* __restrict__ edges,
                          const float* __restrict__ dn, const float* __restrict__ gn) {
    int i = blockIdx.x * blockDim.x + threadIdx.x;
    if (i >= NZ) return;
    int nd = nodes[i];
    int p = atomicAdd(&g_ncur[nd], 1);
    g_nedge[p] = edges[i];
    g_dnp[p] = dn[i];
    g_gnp[p] = gn[i];
}

// ---------------- rowdot (layer-0 e only) ----------------
__global__ void k_rowdot(const float* __restrict__ Mx, const float* __restrict__ vlo,
                         const float* __restrict__ vhi, float* __restrict__ olo,
                         float* __restrict__ ohi, int rows) {
    int t = blockIdx.x * blockDim.x + threadIdx.x;
    int w = t >> 5, lane = t & 31;
    if (w >= rows) return;
    float4 a  = ((const float4*)(Mx + (size_t)w * D))[lane];
    float4 l4 = ((const float4*)vlo)[lane];
    float4 h4 = ((const float4*)vhi)[lane];
    float slo = a.x * l4.x + a.y * l4.y + a.z * l4.z + a.w * l4.w;
    float shi = a.x * h4.x + a.y * h4.y + a.z * h4.z + a.w * h4.w;
#pragma unroll
    for (int o = 16; o > 0; o >>= 1) {
        slo += __shfl_xor_sync(0xffffffffu, slo, o);
        shi += __shfl_xor_sync(0xffffffffu, shi, o);
    }
    if (lane == 0) { olo[w] = slo; ohi[w] = shi; }
}

// ---------------- pass 1: fused attention, lane-distributed scalar math -------
__global__ void __launch_bounds__(256)
k_pass1(const int* __restrict__ nodes,
        const float* __restrict__ dv, const float* __restrict__ gv,
        const float* pab, const float* pwdw, const float* pwdb,
        const float* pwgw, const float* pwgb) {
    int t = blockIdx.x * blockDim.x + threadIdx.x;
    int w = t >> 5, lane = t & 31;
    float cst = *pab + *pwdb + *pwgb;
    float wdw = *pwdw, wgw = *pwgw;
    if (w < NE) {
        int o0 = g_eoff[w], o1 = g_eoff[w + 1];
        float base = g_se1[w] + cst;
        float4 acc = make_float4(0.f, 0.f, 0.f, 0.f);
        float4 acc2 = make_float4(0.f, 0.f, 0.f, 0.f);
        float den = 0.f;
        for (int i0 = o0; i0 < o1; i0 += 32) {
            int i = i0 + lane;
            int ndl = 0;
            float wexp = 0.f;
            if (i < o1) {
                ndl = __ldg(nodes + i);
                wexp = __expf(g_sx1[ndl] + base + dv[i] * wdw + gv[i] * wgw);
                g_sv[i] = wexp;
            }
            den += wexp;
            int cnt = min(32, o1 - i0);
            int k = 0;
            for (; k + 1 < cnt; k += 2) {
                float w0 = __shfl_sync(0xffffffffu, wexp, k);
                int  nd0 = __shfl_sync(0xffffffffu, ndl, k);
                float w1 = __shfl_sync(0xffffffffu, wexp, k + 1);
                int  nd1 = __shfl_sync(0xffffffffu, ndl, k + 1);
                float4 x0 = ((const float4*)(g_x + (size_t)nd0 * D))[lane];
                float4 x1 = ((const float4*)(g_x + (size_t)nd1 * D))[lane];
                acc.x = fmaf(x0.x, w0, acc.x); acc.y = fmaf(x0.y, w0, acc.y);
                acc.z = fmaf(x0.z, w0, acc.z); acc.w = fmaf(x0.w, w0, acc.w);
                acc2.x = fmaf(x1.x, w1, acc2.x); acc2.y = fmaf(x1.y, w1, acc2.y);
                acc2.z = fmaf(x1.z, w1, acc2.z); acc2.w = fmaf(x1.w, w1, acc2.w);
            }
            if (k < cnt) {
                float w0 = __shfl_sync(0xffffffffu, wexp, k);
                int  nd0 = __shfl_sync(0xffffffffu, ndl, k);
                float4 x0 = ((const float4*)(g_x + (size_t)nd0 * D))[lane];
                acc.x = fmaf(x0.x, w0, acc.x); acc.y = fmaf(x0.y, w0, acc.y);
                acc.z = fmaf(x0.z, w0, acc.z); acc.w = fmaf(x0.w, w0, acc.w);
            }
        }
#pragma unroll
        for (int o = 16; o > 0; o >>= 1) den += __shfl_xor_sync(0xffffffffu, den, o);
        if (lane == 0) g_denE[w] = den;
        float s = (o1 > o0) ? g_degE[w] / den : 0.f;
        ((float4*)(g_Xe1 + (size_t)w * D))[lane] =
            make_float4((acc.x + acc2.x) * s, (acc.y + acc2.y) * s,
                        (acc.z + acc2.z) * s, (acc.w + acc2.w) * s);
    } else {
        w -= NE;
        if (w >= NN) return;
        int o0 = g_noff[w], o1 = g_noff[w + 1];
        float base = g_sx2[w] + cst;
        float4 acc = make_float4(0.f, 0.f, 0.f, 0.f);
        float4 acc2 = make_float4(0.f, 0.f, 0.f, 0.f);
        float den = 0.f;
        for (int j0 = o0; j0 < o1; j0 += 32) {
            int j = j0 + lane;
            int edl = 0;
            float wexp = 0.f;
            if (j < o1) {
                edl = __ldg(g_nedge + j);
                wexp = __expf(g_se2[edl] + base + g_dnp[j] * wdw + g_gnp[j] * wgw);
                g_snp[j] = wexp;
            }
            den += wexp;
            int cnt = min(32, o1 - j0);
            int k = 0;
            for (; k + 1 < cnt; k += 2) {
                float w0 = __shfl_sync(0xffffffffu, wexp, k);
                int  ed0 = __shfl_sync(0xffffffffu, edl, k);
                float w1 = __shfl_sync(0xffffffffu, wexp, k + 1);
                int  ed1 = __shfl_sync(0xffffffffu, edl, k + 1);
                float4 e0 = ((const float4*)(g_e + (size_t)ed0 * D))[lane];
                float4 e1 = ((const float4*)(g_e + (size_t)ed1 * D))[lane];
                acc.x = fmaf(e0.x, w0, acc.x); acc.y = fmaf(e0.y, w0, acc.y);
                acc.z = fmaf(e0.z, w0, acc.z); acc.w = fmaf(e0.w, w0, acc.w);
                acc2.x = fmaf(e1.x, w1, acc2.x); acc2.y = fmaf(e1.y, w1, acc2.y);
                acc2.z = fmaf(e1.z, w1, acc2.z); acc2.w = fmaf(e1.w, w1, acc2.w);
            }
            if (k < cnt) {
                float w0 = __shfl_sync(0xffffffffu, wexp, k);
                int  ed0 = __shfl_sync(0xffffffffu, edl, k);
                float4 e0 = ((const float4*)(g_e + (size_t)ed0 * D))[lane];
                acc.x = fmaf(e0.x, w0, acc.x); acc.y = fmaf(e0.y, w0, acc.y);
                acc.z = fmaf(e0.z, w0, acc.z); acc.w = fmaf(e0.w, w0, acc.w);
            }
        }
#pragma unroll
        for (int o = 16; o > 0; o >>= 1) den += __shfl_xor_sync(0xffffffffu, den, o);
        if (lane == 0) g_denN[w] = den;
        float s = (o1 > o0) ? g_degV[w] / den : 0.f;
        ((float4*)(g_Xv2 + (size_t)w * D))[lane] =
            make_float4((acc.x + acc2.x) * s, (acc.y + acc2.y) * s,
                        (acc.z + acc2.z) * s, (acc.w + acc2.w) * s);
    }
}

// ---------------- bf16 split helper ----------------
__device__ __forceinline__ void split_store4(__nv_bfloat16* hi, __nv_bfloat16* lo,
                                             int i, float4 r) {
    __nv_bfloat16 h0 = __float2bfloat16(r.x), h1 = __float2bfloat16(r.y);
    __nv_bfloat16 h2 = __float2bfloat16(r.z), h3 = __float2bfloat16(r.w);
    __nv_bfloat162 a, b;
    a.x = h0; a.y = h1; b.x = h2; b.y = h3;
    ((__nv_bfloat162*)hi)[2 * i] = a; ((__nv_bfloat162*)hi)[2 * i + 1] = b;
    a.x = __float2bfloat16(r.x - __bfloat162float(h0));
    a.y = __float2bfloat16(r.y - __bfloat162float(h1));
    b.x = __float2bfloat16(r.z - __bfloat162float(h2));
    b.y = __float2bfloat16(r.w - __bfloat162float(h3));
    ((__nv_bfloat162*)lo)[2 * i] = a; ((__nv_bfloat162*)lo)[2 * i + 1] = b;
}

// ---------------- pass 2 + fused mixes + bf16 split ---------------------------
__global__ void __launch_bounds__(256)
k_pass2(const int* __restrict__ nodes, const float* __restrict__ e0) {
    int t = blockIdx.x * blockDim.x + threadIdx.x;
    int w = t >> 5, lane = t & 31;
    if (w < NE) {
        int o0 = g_eoff[w], o1 = g_eoff[w + 1];
        float4 acc = make_float4(0.f, 0.f, 0.f, 0.f);
        float4 acc2 = make_float4(0.f, 0.f, 0.f, 0.f);
        int i = o0;
        for (; i + 3 < o1; i += 4) {
            int nd0 = __ldg(nodes + i),     nd1 = __ldg(nodes + i + 1);
            int nd2 = __ldg(nodes + i + 2), nd3 = __ldg(nodes + i + 3);
            float w0 = g_sv[i], w1 = g_sv[i + 1], w2 = g_sv[i + 2], w3 = g_sv[i + 3];
            float4 x0 = ((const float4*)(g_Xv2 + (size_t)nd0 * D))[lane];
            float4 x1 = ((const float4*)(g_Xv2 + (size_t)nd1 * D))[lane];
            float4 x2 = ((const float4*)(g_Xv2 + (size_t)nd2 * D))[lane];
            float4 x3 = ((const float4*)(g_Xv2 + (size_t)nd3 * D))[lane];
            acc.x = fmaf(x0.x, w0, acc.x); acc.y = fmaf(x0.y, w0, acc.y);
            acc.z = fmaf(x0.z, w0, acc.z); acc.w = fmaf(x0.w, w0, acc.w);
            acc2.x = fmaf(x1.x, w1, acc2.x); acc2.y = fmaf(x1.y, w1, acc2.y);
            acc2.z = fmaf(x1.z, w1, acc2.z); acc2.w = fmaf(x1.w, w1, acc2.w);
            acc.x = fmaf(x2.x, w2, acc.x); acc.y = fmaf(x2.y, w2, acc.y);
            acc.z = fmaf(x2.z, w2, acc.z); acc.w = fmaf(x2.w, w2, acc.w);
            acc2.x = fmaf(x3.x, w3, acc2.x); acc2.y = fmaf(x3.y, w3, acc2.y);
            acc2.z = fmaf(x3.z, w3, acc2.z); acc2.w = fmaf(x3.w, w3, acc2.w);
        }
        for (; i < o1; i++) {
            int nd = __ldg(nodes + i);
            float wv = g_sv[i];
            float4 vr = ((const float4*)(g_Xv2 + (size_t)nd * D))[lane];
            acc.x = fmaf(vr.x, wv, acc.x); acc.y = fmaf(vr.y, wv, acc.y);
            acc.z = fmaf(vr.z, wv, acc.z); acc.w = fmaf(vr.w, wv, acc.w);
        }
        float s = (o1 > o0) ? 1.f / g_denE[w] : 0.f;
        float sc = 0.45f * g_degE[w] * s;
        float4 xe1 = ((const float4*)(g_Xe1 + (size_t)w * D))[lane];
        float4 ev  = ((const float4*)(e0 + (size_t)w * D))[lane];
        float4 r;
        r.x = sc * (acc.x + acc2.x) + 0.45f * xe1.x + 0.1f * ev.x;
        r.y = sc * (acc.y + acc2.y) + 0.45f * xe1.y + 0.1f * ev.y;
        r.z = sc * (acc.z + acc2.z) + 0.45f * xe1.z + 0.1f * ev.z;
        r.w = sc * (acc.w + acc2.w) + 0.45f * xe1.w + 0.1f * ev.w;
        split_store4(g_ebh, g_ebl, w * 32 + lane, r);
    } else {
        w -= NE;
        if (w >= NN) return;
        int o0 = g_noff[w], o1 = g_noff[w + 1];
        float4 acc = make_float4(0.f, 0.f, 0.f, 0.f);
        float4 acc2 = make_float4(0.f, 0.f, 0.f, 0.f);
        int j = o0;
        for (; j + 1 < o1; j += 2) {
            int ed0 = __ldg(g_nedge + j), ed1 = __ldg(g_nedge + j + 1);
            float w0 = g_snp[j], w1 = g_snp[j + 1];
            float4 e0r = ((const float4*)(g_Xe1 + (size_t)ed0 * D))[lane];
            float4 e1r = ((const float4*)(g_Xe1 + (size_t)ed1 * D))[lane];
            acc.x = fmaf(e0r.x, w0, acc.x); acc.y = fmaf(e0r.y, w0, acc.y);
            acc.z = fmaf(e0r.z, w0, acc.z); acc.w = fmaf(e0r.w, w0, acc.w);
            acc2.x = fmaf(e1r.x, w1, acc2.x); acc2.y = fmaf(e1r.y, w1, acc2.y);
            acc2.z = fmaf(e1r.z, w1, acc2.z); acc2.w = fmaf(e1r.w, w1, acc2.w);
        }
        if (j < o1) {
            int ed = __ldg(g_nedge + j);
            float wn = g_snp[j];
            float4 xr = ((const float4*)(g_Xe1 + (size_t)ed * D))[lane];
            acc.x = fmaf(xr.x, wn, acc.x); acc.y = fmaf(xr.y, wn, acc.y);
            acc.z = fmaf(xr.z, wn, acc.z); acc.w = fmaf(xr.w, wn, acc.w);
        }
        float s = (o1 > o0) ? 1.f / g_denN[w] : 0.f;
        float sc = 0.45f * g_degV[w] * s;
        float4 v2 = ((const float4*)(g_Xv2 + (size_t)w * D))[lane];
        float4 x0 = ((const float4*)(g_x0 + (size_t)w * D))[lane];
        float4 r;
        r.x = sc * (acc.x + acc2.x) + 0.45f * v2.x + 0.1f * x0.x;
        r.y = sc * (acc.y + acc2.y) + 0.45f * v2.y + 0.1f * x0.y;
        r.z = sc * (acc.z + acc2.z) + 0.45f * v2.z + 0.1f * x0.z;
        r.w = sc * (acc.w + acc2.w) + 0.45f * v2.w + 0.1f * x0.w;
        split_store4(g_ah, g_al, w * 32 + lane, r);
    }
}

// ---------------- launch ----------------
extern "C" void kernel_launch(void* const* d_in, const int* in_sizes, int n_in,
                              void* d_out, int out_size) {
    const float* x_in = (const float*)d_in[0];
    const float* e_in = (const float*)d_in[1];
    const int*   hei  = (const int*)d_in[2];
    const int*   nodes = hei;
    const int*   edges = hei + NZ;
    const float* dv2e = (const float*)d_in[3];
    const float* gv2e = (const float*)d_in[4];
    const float* de2v = (const float*)d_in[5];
    const float* ge2v = (const float*)d_in[6];
    const float* W0   = (const float*)d_in[7];
    const float* b0   = (const float*)d_in[8];
    const float* Wn   = (const float*)d_in[9];
    const float* We   = (const float*)d_in[10];
    const float* aw   = (const float*)d_in[11];
    const float* ab   = (const float*)d_in[12];
    const float* wdw  = (const float*)d_in[13];
    const float* wdb  = (const float*)d_in[14];
    const float* wgw  = (const float*)d_in[15];
    const float* wgb  = (const float*)d_in[16];
    float* out = (float*)d_out;

    cudaFuncSetAttribute(k_gemm0, cudaFuncAttributeMaxDynamicSharedMemorySize, SMEM_MMA);
    cudaFuncSetAttribute(k_gemm2<1>, cudaFuncAttributeMaxDynamicSharedMemorySize, SMEM_MMA);
    cudaFuncSetAttribute(k_gemm2<2>, cudaFuncAttributeMaxDynamicSharedMemorySize, SMEM_MMA);

    void *pncnt;
    void *px, *px0, *pe, *psx1, *psx2, *pse1, *pse2;
    void *pah, *pal, *pebh, *pebl, *pw0h, *pw0l, *pwnh, *pwnl, *pweh, *pwel;
    cudaGetSymbolAddress(&pncnt, g_ncnt);
    cudaGetSymbolAddress(&px, g_x);       cudaGetSymbolAddress(&px0, g_x0);
    cudaGetSymbolAddress(&pe, g_e);
    cudaGetSymbolAddress(&psx1, g_sx1);   cudaGetSymbolAddress(&psx2, g_sx2);
    cudaGetSymbolAddress(&pse1, g_se1);   cudaGetSymbolAddress(&pse2, g_se2);
    cudaGetSymbolAddress(&pah, g_ah);     cudaGetSymbolAddress(&pal, g_al);
    cudaGetSymbolAddress(&pebh, g_ebh);   cudaGetSymbolAddress(&pebl, g_ebl);
    cudaGetSymbolAddress(&pw0h, g_w0h);   cudaGetSymbolAddress(&pw0l, g_w0l);
    cudaGetSymbolAddress(&pwnh, g_wnh);   cudaGetSymbolAddress(&pwnl, g_wnl);
    cudaGetSymbolAddress(&pweh, g_weh);   cudaGetSymbolAddress(&pwel, g_wel);

    const int B = 256;
    const int gNZ   = (NZ + B - 1) / B;
    const int gEW   = (NE * 32 + B - 1) / B;
    const int gPASS = ((NE + NN) * 32 + B - 1) / B;
    const int gXT   = (NN + 63) / 64;
    const int gET   = (NE + 63) / 64;
    const int gCW   = ((1 + 2 * NL) * D * D + B - 1) / B;

    // ---- one-time setup ----
    cudaMemsetAsync(pncnt, 0, NN * 4, 0);
    k_count<<<gNZ, B>>>(nodes);
    k_eoff2<<<gNZ, B>>>(edges);
    k_degE<<<gEW, B>>>(nodes);
    k_scan<<<1, 1024>>>();
    k_scatter<<<gNZ, B>>>(nodes, edges, de2v, ge2v);
    k_cvt_allw<<<gCW, B>>>(W0, Wn, We);

    k_cvt_rows<<<(NN * D / 4 + B - 1) / B, B>>>(x_in, (__nv_bfloat16*)pah, (__nv_bfloat16*)pal,
                                                NN * D / 4);
    k_gemm0<<<gXT, 256, SMEM_MMA>>>((__nv_bfloat16*)pah, (__nv_bfloat16*)pal,
                                    (__nv_bfloat16*)pw0h, (__nv_bfloat16*)pw0l,
                                    b0, (float*)px, (float*)px0, NN,
                                    aw, (float*)psx1, (float*)psx2);
    cudaMemcpyAsync(pe, e_in, (size_t)NE * D * 4, cudaMemcpyDeviceToDevice, 0);
    k_rowdot<<<(NE * 32 + B - 1) / B, B>>>(e_in, aw, aw + D, (float*)pse2, (float*)pse1, NE);

    bool both = (out_size >= (NN + NE) * D);

    for (int l = 0; l < NL; l++) {
        float beta = logf(0.5f / (float)(l + 1) + 1.f);

        k_pass1<<<gPASS, B>>>(nodes, dv2e, gv2e,
                              ab + l, wdw + l, wdb + l, wgw + l, wgb + l);
        k_pass2<<<gPASS, B>>>(nodes, e_in);

        GP gx, ge;
        gx.Ah = (__nv_bfloat16*)pah; gx.Al = (__nv_bfloat16*)pal;
        gx.Bh = (__nv_bfloat16*)pwnh + (size_t)l * D * D;
        gx.Bl = (__nv_bfloat16*)pwnl + (size_t)l * D * D;
        gx.M = NN; gx.nblk = gXT;
        gx.dlo = (float*)psx1; gx.dhi = (float*)psx2;
        ge.Ah = (__nv_bfloat16*)pebh; ge.Al = (__nv_bfloat16*)pebl;
        ge.Bh = (__nv_bfloat16*)pweh + (size_t)l * D * D;
        ge.Bl = (__nv_bfloat16*)pwel + (size_t)l * D * D;
        ge.M = NE; ge.nblk = gET;
        ge.dlo = (float*)pse2; ge.dhi = (float*)pse1;

        if (l < NL - 1) {
            gx.C = (float*)px;
            ge.C = (float*)pe;
            const float* awn = aw + (size_t)(l + 1) * 2 * D;
            k_gemm2<1><<<gXT + gET, 256, SMEM_MMA>>>(gx, ge, beta, awn);
        } else {
            gx.C = out;
            ge.C = both ? out + (size_t)NN * D : (float*)pe;
            k_gemm2<2><<<gXT + gET, 256, SMEM_MMA>>>(gx, ge, beta, nullptr);
        }
    }
}

// round 16
// speedup vs baseline: 1.1370x; 1.0653x over previous
#include <cuda_runtime.h>
#include <cuda_bf16.h>
#include <math.h>
#include <stdint.h>

#define NN 100000
#define NE 20000
#define NZ 500000
#define D  128
#define NL 4
#define SCAN_B 1024
#define SCAN_NBLK ((NN + SCAN_B - 1) / SCAN_B)   // 98

// ---------------- scratch ----------------
__device__ float g_degV[NN], g_denN[NN], g_sx1[NN], g_sx2[NN];
__device__ float g_degE[NE], g_denE[NE], g_se1[NE], g_se2[NE];
__device__ int   g_eoff[NE + 1];
__device__ int   g_ncnt[NN], g_noff[NN + 1], g_ncur[NN];
__device__ int   g_bsum[SCAN_NBLK];
__device__ int   g_nedge[NZ];
__device__ float g_dnp[NZ], g_gnp[NZ];
__device__ float g_x [NN * D];
__device__ float g_x0[NN * D];
__device__ float g_Xv2[NN * D];
__device__ float g_e [NE * D];
__device__ float g_Xe1[NE * D];
__device__ float g_sv[NZ], g_snp[NZ];
__device__ __nv_bfloat16 g_ah[NN * D], g_al[NN * D];
__device__ __nv_bfloat16 g_ebh[NE * D], g_ebl[NE * D];
__device__ __nv_bfloat16 g_w0h[D * D], g_w0l[D * D];
__device__ __nv_bfloat16 g_wnh[NL * D * D], g_wnl[NL * D * D];
__device__ __nv_bfloat16 g_weh[NL * D * D], g_wel[NL * D * D];

// ---------------- mma / cp.async helpers (portable sm_80+ PTX) ----------------
__device__ __forceinline__ uint32_t s2u(const void* p) {
    uint32_t a;
    asm("{ .reg .u64 t; cvta.to.shared.u64 t, %1; cvt.u32.u64 %0, t; }" : "=r"(a) : "l"(p));
    return a;
}
__device__ __forceinline__ void ldsm4(uint32_t& r0, uint32_t& r1, uint32_t& r2, uint32_t& r3,
                                      uint32_t addr) {
    asm volatile("ldmatrix.sync.aligned.m8n8.x4.shared.b16 {%0,%1,%2,%3}, [%4];"
                 : "=r"(r0), "=r"(r1), "=r"(r2), "=r"(r3) : "r"(addr));
}
__device__ __forceinline__ void mma_bf16(float* c, const uint32_t* a, const uint32_t* b) {
    asm volatile("mma.sync.aligned.m16n8k16.row.col.f32.bf16.bf16.f32 "
                 "{%0,%1,%2,%3}, {%4,%5,%6,%7}, {%8,%9}, {%0,%1,%2,%3};"
                 : "+f"(c[0]), "+f"(c[1]), "+f"(c[2]), "+f"(c[3])
                 : "r"(a[0]), "r"(a[1]), "r"(a[2]), "r"(a[3]), "r"(b[0]), "r"(b[1]));
}
__device__ __forceinline__ void cpa16(uint32_t dst, const void* src, bool pred) {
    int sz = pred ? 16 : 0;
    asm volatile("cp.async.cg.shared.global [%0], [%1], 16, %2;"
                 :: "r"(dst), "l"(src), "r"(sz) : "memory");
}
__device__ __forceinline__ void cp_commit() {
    asm volatile("cp.async.commit_group;" ::: "memory");
}
template<int N>
__device__ __forceinline__ void cp_wait() {
    asm volatile("cp.async.wait_group %0;" :: "n"(N) : "memory");
}

// smem tiles: A = 64 rows, B = 128 rows, stride 136 bf16
#define TSTRIDE 136
#define ATILEB  (64 * TSTRIDE * 2)
#define BTILEB  (128 * TSTRIDE * 2)
#define SM_AH   0
#define SM_AL   (ATILEB)
#define SM_BH   (2 * ATILEB)
#define SM_BL   (2 * ATILEB + BTILEB)
#define SM_AW   (2 * ATILEB + 2 * BTILEB)
#define SM_BIAS (SM_AW + 1024)
#define SM_DLO  (SM_BIAS + 512)
#define SM_DHI  (SM_DLO + 512)
#define SMEM_MMA (SM_DHI + 512)

__device__ __forceinline__ void load_tileA(const __nv_bfloat16* __restrict__ g,
                                           int row0, int Mlim, uint32_t sb, int soff) {
    for (int idx = threadIdx.x; idx < 1024; idx += 256) {
        int r = idx >> 4;
        int c8 = (idx & 15) << 3;
        int gr = row0 + r;
        bool ok = gr < Mlim;
        int gs = ok ? gr : 0;
        cpa16(sb + soff + (uint32_t)((r * TSTRIDE + c8) * 2), g + (size_t)gs * D + c8, ok);
    }
}
__device__ __forceinline__ void load_tileB(const __nv_bfloat16* __restrict__ g,
                                           uint32_t sb, int soff) {
    for (int idx = threadIdx.x; idx < 2048; idx += 256) {
        int r = idx >> 4;
        int c8 = (idx & 15) << 3;
        cpa16(sb + soff + (uint32_t)((r * TSTRIDE + c8) * 2), g + (size_t)r * D + c8, true);
    }
}

struct GP {
    const __nv_bfloat16 *Ah, *Al, *Bh, *Bl;
    float* C;
    float* dlo;
    float* dhi;
    int M;
    int nblk;
};

// ---------------- GEMM core (bf16x3, fp32 acc, 64-row tile) --------------------
template<int MODE>
__device__ __forceinline__ void gemm_body(
    const __nv_bfloat16* __restrict__ Ah, const __nv_bfloat16* __restrict__ Al,
    const __nv_bfloat16* __restrict__ Bh, const __nv_bfloat16* __restrict__ Bl,
    const float* __restrict__ bias, float beta,
    float* __restrict__ C, float* __restrict__ C2, int M, int m0,
    const float* __restrict__ awrow, float* __restrict__ dlo, float* __restrict__ dhi,
    char* smem) {
    const int tid = threadIdx.x, lane = tid & 31, wid = tid >> 5;
    const int wm = wid >> 1, wn = wid & 1;
    uint32_t sb = s2u(smem);

    load_tileA(Ah, m0, M, sb, SM_AH);
    load_tileB(Bh, sb, SM_BH);
    cp_commit();
    load_tileA(Al, m0, M, sb, SM_AL);
    load_tileB(Bl, sb, SM_BL);
    cp_commit();

    float* s_aw = (float*)(smem + SM_AW);
    float* s_bias = (float*)(smem + SM_BIAS);
    float* s_lo = (float*)(smem + SM_DLO);
    float* s_hi = (float*)(smem + SM_DHI);
    if (MODE != 2) { if (tid < 256) s_aw[tid] = awrow[tid]; }
    if (MODE == 0) { if (tid < 128) s_bias[tid] = bias[tid]; }

    cp_wait<1>();
    __syncthreads();

    float acc[8][4];
#pragma unroll
    for (int nt = 0; nt < 8; nt++)
#pragma unroll
        for (int q = 0; q < 4; q++) acc[nt][q] = 0.f;

    const int a_row16 = (lane & 7) + (((lane >> 3) & 1) << 3);
    const int a_col   = ((lane >> 4) & 1) << 3;
    const int b_nin   = (lane & 7) + (((lane >> 4) & 1) << 3);
    const int b_col   = ((lane >> 3) & 1) << 3;

    const int apass[3] = {SM_AH, SM_AH, SM_AL};
    const int bpass[3] = {SM_BH, SM_BL, SM_BH};

#pragma unroll
    for (int p = 0; p < 3; p++) {
        if (p == 1) { cp_wait<0>(); __syncthreads(); }
        uint32_t aoff = sb + apass[p];
        uint32_t boff = sb + bpass[p];
#pragma unroll
        for (int ks = 0; ks < 8; ks++) {
            uint32_t a[4];
            {
                uint32_t addr = aoff + (uint32_t)(((wm * 16 + a_row16) * TSTRIDE
                                                  + ks * 16 + a_col) * 2);
                ldsm4(a[0], a[1], a[2], a[3], addr);
            }
            uint32_t b[8][2];
#pragma unroll
            for (int ntp = 0; ntp < 4; ntp++) {
                uint32_t addr = boff + (uint32_t)(((wn * 64 + ntp * 16 + b_nin) * TSTRIDE
                                                  + ks * 16 + b_col) * 2);
                ldsm4(b[2 * ntp][0], b[2 * ntp][1], b[2 * ntp + 1][0], b[2 * ntp + 1][1], addr);
            }
#pragma unroll
            for (int nt = 0; nt < 8; nt++)
                mma_bf16(acc[nt], a, b[nt]);
        }
    }

    const float ob = 1.f - beta;
    const __nv_bfloat162* sAh2 = (const __nv_bfloat162*)(smem + SM_AH);
    const __nv_bfloat162* sAl2 = (const __nv_bfloat162*)(smem + SM_AL);
    float slo[2] = {0.f, 0.f}, shi[2] = {0.f, 0.f};
#pragma unroll
    for (int nt = 0; nt < 8; nt++) {
        int col = wn * 64 + nt * 8 + (lane & 3) * 2;
        int lr0 = wm * 16 + (lane >> 2);
        int lr1 = lr0 + 8;
        int r0 = m0 + lr0;
        int r1 = m0 + lr1;
        float2 v0 = make_float2(acc[nt][0], acc[nt][1]);
        float2 v1 = make_float2(acc[nt][2], acc[nt][3]);
        if (MODE == 0) {
            float2 bb = *(const float2*)(s_bias + col);
            v0.x = fmaxf(v0.x + bb.x, 0.f); v0.y = fmaxf(v0.y + bb.y, 0.f);
            v1.x = fmaxf(v1.x + bb.x, 0.f); v1.y = fmaxf(v1.y + bb.y, 0.f);
            if (r0 < M) { *(float2*)(C + (size_t)r0 * D + col) = v0;
                          *(float2*)(C2 + (size_t)r0 * D + col) = v0; }
            if (r1 < M) { *(float2*)(C + (size_t)r1 * D + col) = v1;
                          *(float2*)(C2 + (size_t)r1 * D + col) = v1; }
        } else {
            int idx0 = (lr0 * TSTRIDE + col) >> 1;
            int idx1 = (lr1 * TSTRIDE + col) >> 1;
            __nv_bfloat162 h0 = sAh2[idx0], l0 = sAl2[idx0];
            __nv_bfloat162 h1 = sAh2[idx1], l1 = sAl2[idx1];
            float2 a0 = make_float2(__bfloat162float(h0.x) + __bfloat162float(l0.x),
                                    __bfloat162float(h0.y) + __bfloat162float(l0.y));
            float2 a1 = make_float2(__bfloat162float(h1.x) + __bfloat162float(l1.x),
                                    __bfloat162float(h1.y) + __bfloat162float(l1.y));
            v0.x = ob * a0.x + beta * v0.x; v0.y = ob * a0.y + beta * v0.y;
            v1.x = ob * a1.x + beta * v1.x; v1.y = ob * a1.y + beta * v1.y;
            if (MODE == 1) {
                v0.x = fmaxf(v0.x, 0.f); v0.y = fmaxf(v0.y, 0.f);
                v1.x = fmaxf(v1.x, 0.f); v1.y = fmaxf(v1.y, 0.f);
            }
            if (r0 < M) *(float2*)(C + (size_t)r0 * D + col) = v0;
            if (r1 < M) *(float2*)(C + (size_t)r1 * D + col) = v1;
        }
        if (MODE != 2) {
            float2 wl = *(const float2*)(s_aw + col);
            float2 wh = *(const float2*)(s_aw + 128 + col);
            slo[0] += v0.x * wl.x + v0.y * wl.y;
            shi[0] += v0.x * wh.x + v0.y * wh.y;
            slo[1] += v1.x * wl.x + v1.y * wl.y;
            shi[1] += v1.x * wh.x + v1.y * wh.y;
        }
    }
    if (MODE != 2) {
#pragma unroll
        for (int q = 0; q < 2; q++) {
            slo[q] += __shfl_xor_sync(0xffffffffu, slo[q], 1);
            slo[q] += __shfl_xor_sync(0xffffffffu, slo[q], 2);
            shi[q] += __shfl_xor_sync(0xffffffffu, shi[q], 1);
            shi[q] += __shfl_xor_sync(0xffffffffu, shi[q], 2);
        }
        if ((lane & 3) == 0) {
#pragma unroll
            for (int q = 0; q < 2; q++) {
                int lrow = wm * 16 + (lane >> 2) + q * 8;
                s_lo[lrow * 2 + wn] = slo[q];
                s_hi[lrow * 2 + wn] = shi[q];
            }
        }
        __syncthreads();
        if (tid < 64) {
            int grow = m0 + tid;
            if (grow < M) {
                dlo[grow] = s_lo[tid * 2] + s_lo[tid * 2 + 1];
                dhi[grow] = s_hi[tid * 2] + s_hi[tid * 2 + 1];
            }
        }
    }
}

__global__ void __launch_bounds__(256, 2)
k_gemm0(const __nv_bfloat16* __restrict__ Ah, const __nv_bfloat16* __restrict__ Al,
        const __nv_bfloat16* __restrict__ Bh, const __nv_bfloat16* __restrict__ Bl,
        const float* __restrict__ bias, float* __restrict__ C, float* __restrict__ C2,
        int M, const float* __restrict__ awrow, float* __restrict__ dlo,
        float* __restrict__ dhi) {
    extern __shared__ char smem[];
    gemm_body<0>(Ah, Al, Bh, Bl, bias, 0.f, C, C2, M, blockIdx.x * 64,
                 awrow, dlo, dhi, smem);
}
template<int MODE>
__global__ void __launch_bounds__(256, 2)
k_gemm2(GP ga, GP gb, float beta, const float* __restrict__ awrow) {
    extern __shared__ char smem[];
    bool isA = blockIdx.x < (unsigned)ga.nblk;
    GP g = isA ? ga : gb;
    int m0 = (isA ? blockIdx.x : blockIdx.x - ga.nblk) * 64;
    gemm_body<MODE>(g.Ah, g.Al, g.Bh, g.Bl, nullptr, beta, g.C, nullptr,
                    g.M, m0, awrow, g.dlo, g.dhi, smem);
}

// ---------------- conversions ----------------
__global__ void k_cvt_rows(const float* __restrict__ src, __nv_bfloat16* __restrict__ hi,
                           __nv_bfloat16* __restrict__ lo, int n4) {
    int i = blockIdx.x * blockDim.x + threadIdx.x;
    if (i >= n4) return;
    float4 v = ((const float4*)src)[i];
    __nv_bfloat16 h0 = __float2bfloat16(v.x), h1 = __float2bfloat16(v.y);
    __nv_bfloat16 h2 = __float2bfloat16(v.z), h3 = __float2bfloat16(v.w);
    __nv_bfloat162 a, b;
    a.x = h0; a.y = h1; b.x = h2; b.y = h3;
    ((__nv_bfloat162*)hi)[2 * i] = a; ((__nv_bfloat162*)hi)[2 * i + 1] = b;
    a.x = __float2bfloat16(v.x - __bfloat162float(h0));
    a.y = __float2bfloat16(v.y - __bfloat162float(h1));
    b.x = __float2bfloat16(v.z - __bfloat162float(h2));
    b.y = __float2bfloat16(v.w - __bfloat162float(h3));
    ((__nv_bfloat162*)lo)[2 * i] = a; ((__nv_bfloat162*)lo)[2 * i + 1] = b;
}
__global__ void k_cvt_allw(const float* __restrict__ W0,
                           const float* __restrict__ Wn, const float* __restrict__ We) {
    int i = blockIdx.x * blockDim.x + threadIdx.x;
    int total = (1 + 2 * NL) * D * D;
    if (i >= total) return;
    int m = i / (D * D);
    int j = i - m * (D * D);
    int n = j >> 7, k = j & 127;
    const float* W;
    __nv_bfloat16 *hi, *lo;
    if (m == 0) { W = W0; hi = g_w0h; lo = g_w0l; }
    else if (m <= NL) {
        int l = m - 1;
        W = Wn + (size_t)l * D * D; hi = g_wnh + (size_t)l * D * D; lo = g_wnl + (size_t)l * D * D;
    } else {
        int l = m - NL - 1;
        W = We + (size_t)l * D * D; hi = g_weh + (size_t)l * D * D; lo = g_wel + (size_t)l * D * D;
    }
    float v = W[(size_t)k * D + n];
    __nv_bfloat16 h = __float2bfloat16(v);
    hi[j] = h;
    lo[j] = __float2bfloat16(v - __bfloat162float(h));
}

// ---------------- degrees / CSR setup ----------------
__global__ void k_count(const int* __restrict__ nodes) {
    int i = blockIdx.x * blockDim.x + threadIdx.x;
    if (i >= NZ) return;
    atomicAdd(&g_ncnt[nodes[i]], 1);
}
__global__ void k_eoff2(const int* __restrict__ edges) {
    int i = blockIdx.x * blockDim.x + threadIdx.x;
    if (i >= NZ) return;
    int e1 = edges[i];
    int e0 = (i == 0) ? -1 : edges[i - 1];
    for (int e = e0 + 1; e <= e1; e++) g_eoff[e] = i;
    if (i == NZ - 1)
        for (int e = e1 + 1; e <= NE; e++) g_eoff[e] = NZ;
}
__global__ void k_degE(const int* __restrict__ nodes) {
    int t = blockIdx.x * blockDim.x + threadIdx.x;
    int w = t >> 5, lane = t & 31;
    if (w >= NE) return;
    int o0 = g_eoff[w], o1 = g_eoff[w + 1];
    float s = 0.f;
    for (int i = o0 + lane; i < o1; i += 32)
        s += (float)__ldg(g_ncnt + __ldg(nodes + i));
#pragma unroll
    for (int o = 16; o > 0; o >>= 1) s += __shfl_xor_sync(0xffffffffu, s, o);
    if (lane == 0) {
        float cnt = (float)(o1 - o0);
        float de = s / fmaxf(cnt, 1.f);
        g_degE[w] = (de > 0.f) ? rsqrtf(de) : 1.f;
    }
}
// ---- 3-phase parallel scan of g_ncnt -> g_noff (+ degV in phase 1) ----
__global__ void __launch_bounds__(SCAN_B)
k_scan1() {
    __shared__ int warpsum[32];
    const int tid = threadIdx.x, lane = tid & 31, wid = tid >> 5;
    int i = blockIdx.x * SCAN_B + tid;
    int v = (i < NN) ? g_ncnt[i] : 0;
    if (i < NN) g_degV[i] = (v > 0) ? rsqrtf((float)v) : 1.f;
    int x = v;
#pragma unroll
    for (int o = 1; o < 32; o <<= 1) {
        int y = __shfl_up_sync(0xffffffffu, x, o);
        if (lane >= o) x += y;
    }
    if (lane == 31) warpsum[wid] = x;
    __syncthreads();
    if (wid == 0) {
        int s = (lane < 32) ? warpsum[lane] : 0;
#pragma unroll
        for (int o = 1; o < 32; o <<= 1) {
            int y = __shfl_up_sync(0xffffffffu, s, o);
            if (lane >= o) s += y;
        }
        warpsum[lane] = s;
    }
    __syncthreads();
    int pref = (wid > 0) ? warpsum[wid - 1] : 0;
    if (i < NN) g_noff[i] = pref + x - v;     // block-local exclusive
    if (tid == SCAN_B - 1) g_bsum[blockIdx.x] = pref + x;
}
__global__ void k_scan2() {
    // single warp scans SCAN_NBLK (<=128) block totals, exclusive, in place
    const int lane = threadIdx.x;
    int run = 0;
    for (int base = 0; base < SCAN_NBLK; base += 32) {
        int idx = base + lane;
        int v = (idx < SCAN_NBLK) ? g_bsum[idx] : 0;
        int x = v;
#pragma unroll
        for (int o = 1; o < 32; o <<= 1) {
            int y = __shfl_up_sync(0xffffffffu, x, o);
            if (lane >= o) x += y;
        }
        if (idx < SCAN_NBLK) g_bsum[idx] = run + x - v;
        int tot = __shfl_sync(0xffffffffu, x, 31);
        run += tot;
    }
}
__global__ void k_scan3() {
    int i = blockIdx.x * blockDim.x + threadIdx.x;
    if (i >= NN) return;
    int off = g_noff[i] + g_bsum[i / SCAN_B];
    g_noff[i] = off;
    g_ncur[i] = off;
    if (i == 0) g_noff[NN] = NZ;
}
__global__ void k_scatter(const int* __restrict__ nodes, const int* __restrict__ edges,
                          const float* __restrict__ dn, const float* __restrict__ gn) {
    int i = blockIdx.x * blockDim.x + threadIdx.x;
    if (i >= NZ) return;
    int nd = nodes[i];
    int p = atomicAdd(&g_ncur[nd], 1);
    g_nedge[p] = edges[i];
    g_dnp[p] = dn[i];
    g_gnp[p] = gn[i];
}

// ---------------- rowdot (layer-0 e only) ----------------
__global__ void k_rowdot(const float* __restrict__ Mx, const float* __restrict__ vlo,
                         const float* __restrict__ vhi, float* __restrict__ olo,
                         float* __restrict__ ohi, int rows) {
    int t = blockIdx.x * blockDim.x + threadIdx.x;
    int w = t >> 5, lane = t & 31;
    if (w >= rows) return;
    float4 a  = ((const float4*)(Mx + (size_t)w * D))[lane];
    float4 l4 = ((const float4*)vlo)[lane];
    float4 h4 = ((const float4*)vhi)[lane];
    float slo = a.x * l4.x + a.y * l4.y + a.z * l4.z + a.w * l4.w;
    float shi = a.x * h4.x + a.y * h4.y + a.z * h4.z + a.w * h4.w;
#pragma unroll
    for (int o = 16; o > 0; o >>= 1) {
        slo += __shfl_xor_sync(0xffffffffu, slo, o);
        shi += __shfl_xor_sync(0xffffffffu, shi, o);
    }
    if (lane == 0) { olo[w] = slo; ohi[w] = shi; }
}

// ---------------- pass 1: fused attention, lane-distributed scalar math -------
__global__ void __launch_bounds__(256)
k_pass1(const int* __restrict__ nodes,
        const float* __restrict__ dv, const float* __restrict__ gv,
        const float* pab, const float* pwdw, const float* pwdb,
        const float* pwgw, const float* pwgb) {
    int t = blockIdx.x * blockDim.x + threadIdx.x;
    int w = t >> 5, lane = t & 31;
    float cst = *pab + *pwdb + *pwgb;
    float wdw = *pwdw, wgw = *pwgw;
    if (w < NE) {
        int o0 = g_eoff[w], o1 = g_eoff[w + 1];
        float base = g_se1[w] + cst;
        float4 acc = make_float4(0.f, 0.f, 0.f, 0.f);
        float4 acc2 = make_float4(0.f, 0.f, 0.f, 0.f);
        float den = 0.f;
        for (int i0 = o0; i0 < o1; i0 += 32) {
            int i = i0 + lane;
            int ndl = 0;
            float wexp = 0.f;
            if (i < o1) {
                ndl = __ldg(nodes + i);
                wexp = __expf(g_sx1[ndl] + base + dv[i] * wdw + gv[i] * wgw);
                g_sv[i] = wexp;
            }
            den += wexp;
            int cnt = min(32, o1 - i0);
            int k = 0;
            for (; k + 1 < cnt; k += 2) {
                float w0 = __shfl_sync(0xffffffffu, wexp, k);
                int  nd0 = __shfl_sync(0xffffffffu, ndl, k);
                float w1 = __shfl_sync(0xffffffffu, wexp, k + 1);
                int  nd1 = __shfl_sync(0xffffffffu, ndl, k + 1);
                float4 x0 = ((const float4*)(g_x + (size_t)nd0 * D))[lane];
                float4 x1 = ((const float4*)(g_x + (size_t)nd1 * D))[lane];
                acc.x = fmaf(x0.x, w0, acc.x); acc.y = fmaf(x0.y, w0, acc.y);
                acc.z = fmaf(x0.z, w0, acc.z); acc.w = fmaf(x0.w, w0, acc.w);
                acc2.x = fmaf(x1.x, w1, acc2.x); acc2.y = fmaf(x1.y, w1, acc2.y);
                acc2.z = fmaf(x1.z, w1, acc2.z); acc2.w = fmaf(x1.w, w1, acc2.w);
            }
            if (k < cnt) {
                float w0 = __shfl_sync(0xffffffffu, wexp, k);
                int  nd0 = __shfl_sync(0xffffffffu, ndl, k);
                float4 x0 = ((const float4*)(g_x + (size_t)nd0 * D))[lane];
                acc.x = fmaf(x0.x, w0, acc.x); acc.y = fmaf(x0.y, w0, acc.y);
                acc.z = fmaf(x0.z, w0, acc.z); acc.w = fmaf(x0.w, w0, acc.w);
            }
        }
#pragma unroll
        for (int o = 16; o > 0; o >>= 1) den += __shfl_xor_sync(0xffffffffu, den, o);
        if (lane == 0) g_denE[w] = den;
        float s = (o1 > o0) ? g_degE[w] / den : 0.f;
        ((float4*)(g_Xe1 + (size_t)w * D))[lane] =
            make_float4((acc.x + acc2.x) * s, (acc.y + acc2.y) * s,
                        (acc.z + acc2.z) * s, (acc.w + acc2.w) * s);
    } else {
        w -= NE;
        if (w >= NN) return;
        int o0 = g_noff[w], o1 = g_noff[w + 1];
        float base = g_sx2[w] + cst;
        float4 acc = make_float4(0.f, 0.f, 0.f, 0.f);
        float4 acc2 = make_float4(0.f, 0.f, 0.f, 0.f);
        float den = 0.f;
        for (int j0 = o0; j0 < o1; j0 += 32) {
            int j = j0 + lane;
            int edl = 0;
            float wexp = 0.f;
            if (j < o1) {
                edl = __ldg(g_nedge + j);
                wexp = __expf(g_se2[edl] + base + g_dnp[j] * wdw + g_gnp[j] * wgw);
                g_snp[j] = wexp;
            }
            den += wexp;
            int cnt = min(32, o1 - j0);
            int k = 0;
            for (; k + 1 < cnt; k += 2) {
                float w0 = __shfl_sync(0xffffffffu, wexp, k);
                int  ed0 = __shfl_sync(0xffffffffu, edl, k);
                float w1 = __shfl_sync(0xffffffffu, wexp, k + 1);
                int  ed1 = __shfl_sync(0xffffffffu, edl, k + 1);
                float4 e0 = ((const float4*)(g_e + (size_t)ed0 * D))[lane];
                float4 e1 = ((const float4*)(g_e + (size_t)ed1 * D))[lane];
                acc.x = fmaf(e0.x, w0, acc.x); acc.y = fmaf(e0.y, w0, acc.y);
                acc.z = fmaf(e0.z, w0, acc.z); acc.w = fmaf(e0.w, w0, acc.w);
                acc2.x = fmaf(e1.x, w1, acc2.x); acc2.y = fmaf(e1.y, w1, acc2.y);
                acc2.z = fmaf(e1.z, w1, acc2.z); acc2.w = fmaf(e1.w, w1, acc2.w);
            }
            if (k < cnt) {
                float w0 = __shfl_sync(0xffffffffu, wexp, k);
                int  ed0 = __shfl_sync(0xffffffffu, edl, k);
                float4 e0 = ((const float4*)(g_e + (size_t)ed0 * D))[lane];
                acc.x = fmaf(e0.x, w0, acc.x); acc.y = fmaf(e0.y, w0, acc.y);
                acc.z = fmaf(e0.z, w0, acc.z); acc.w = fmaf(e0.w, w0, acc.w);
            }
        }
#pragma unroll
        for (int o = 16; o > 0; o >>= 1) den += __shfl_xor_sync(0xffffffffu, den, o);
        if (lane == 0) g_denN[w] = den;
        float s = (o1 > o0) ? g_degV[w] / den : 0.f;
        ((float4*)(g_Xv2 + (size_t)w * D))[lane] =
            make_float4((acc.x + acc2.x) * s, (acc.y + acc2.y) * s,
                        (acc.z + acc2.z) * s, (acc.w + acc2.w) * s);
    }
}

// ---------------- bf16 split helper ----------------
__device__ __forceinline__ void split_store4(__nv_bfloat16* hi, __nv_bfloat16* lo,
                                             int i, float4 r) {
    __nv_bfloat16 h0 = __float2bfloat16(r.x), h1 = __float2bfloat16(r.y);
    __nv_bfloat16 h2 = __float2bfloat16(r.z), h3 = __float2bfloat16(r.w);
    __nv_bfloat162 a, b;
    a.x = h0; a.y = h1; b.x = h2; b.y = h3;
    ((__nv_bfloat162*)hi)[2 * i] = a; ((__nv_bfloat162*)hi)[2 * i + 1] = b;
    a.x = __float2bfloat16(r.x - __bfloat162float(h0));
    a.y = __float2bfloat16(r.y - __bfloat162float(h1));
    b.x = __float2bfloat16(r.z - __bfloat162float(h2));
    b.y = __float2bfloat16(r.w - __bfloat162float(h3));
    ((__nv_bfloat162*)lo)[2 * i] = a; ((__nv_bfloat162*)lo)[2 * i + 1] = b;
}

// ---------------- pass 2 + fused mixes + bf16 split ---------------------------
__global__ void __launch_bounds__(256)
k_pass2(const int* __restrict__ nodes, const float* __restrict__ e0) {
    int t = blockIdx.x * blockDim.x + threadIdx.x;
    int w = t >> 5, lane = t & 31;
    if (w < NE) {
        int o0 = g_eoff[w], o1 = g_eoff[w + 1];
        float4 acc = make_float4(0.f, 0.f, 0.f, 0.f);
        float4 acc2 = make_float4(0.f, 0.f, 0.f, 0.f);
        int i = o0;
        for (; i + 3 < o1; i += 4) {
            int nd0 = __ldg(nodes + i),     nd1 = __ldg(nodes + i + 1);
            int nd2 = __ldg(nodes + i + 2), nd3 = __ldg(nodes + i + 3);
            float w0 = g_sv[i], w1 = g_sv[i + 1], w2 = g_sv[i + 2], w3 = g_sv[i + 3];
            float4 x0 = ((const float4*)(g_Xv2 + (size_t)nd0 * D))[lane];
            float4 x1 = ((const float4*)(g_Xv2 + (size_t)nd1 * D))[lane];
            float4 x2 = ((const float4*)(g_Xv2 + (size_t)nd2 * D))[lane];
            float4 x3 = ((const float4*)(g_Xv2 + (size_t)nd3 * D))[lane];
            acc.x = fmaf(x0.x, w0, acc.x); acc.y = fmaf(x0.y, w0, acc.y);
            acc.z = fmaf(x0.z, w0, acc.z); acc.w = fmaf(x0.w, w0, acc.w);
            acc2.x = fmaf(x1.x, w1, acc2.x); acc2.y = fmaf(x1.y, w1, acc2.y);
            acc2.z = fmaf(x1.z, w1, acc2.z); acc2.w = fmaf(x1.w, w1, acc2.w);
            acc.x = fmaf(x2.x, w2, acc.x); acc.y = fmaf(x2.y, w2, acc.y);
            acc.z = fmaf(x2.z, w2, acc.z); acc.w = fmaf(x2.w, w2, acc.w);
            acc2.x = fmaf(x3.x, w3, acc2.x); acc2.y = fmaf(x3.y, w3, acc2.y);
            acc2.z = fmaf(x3.z, w3, acc2.z); acc2.w = fmaf(x3.w, w3, acc2.w);
        }
        for (; i < o1; i++) {
            int nd = __ldg(nodes + i);
            float wv = g_sv[i];
            float4 vr = ((const float4*)(g_Xv2 + (size_t)nd * D))[lane];
            acc.x = fmaf(vr.x, wv, acc.x); acc.y = fmaf(vr.y, wv, acc.y);
            acc.z = fmaf(vr.z, wv, acc.z); acc.w = fmaf(vr.w, wv, acc.w);
        }
        float s = (o1 > o0) ? 1.f / g_denE[w] : 0.f;
        float sc = 0.45f * g_degE[w] * s;
        float4 xe1 = ((const float4*)(g_Xe1 + (size_t)w * D))[lane];
        float4 ev  = ((const float4*)(e0 + (size_t)w * D))[lane];
        float4 r;
        r.x = sc * (acc.x + acc2.x) + 0.45f * xe1.x + 0.1f * ev.x;
        r.y = sc * (acc.y + acc2.y) + 0.45f * xe1.y + 0.1f * ev.y;
        r.z = sc * (acc.z + acc2.z) + 0.45f * xe1.z + 0.1f * ev.z;
        r.w = sc * (acc.w + acc2.w) + 0.45f * xe1.w + 0.1f * ev.w;
        split_store4(g_ebh, g_ebl, w * 32 + lane, r);
    } else {
        w -= NE;
        if (w >= NN) return;
        int o0 = g_noff[w], o1 = g_noff[w + 1];
        float4 acc = make_float4(0.f, 0.f, 0.f, 0.f);
        float4 acc2 = make_float4(0.f, 0.f, 0.f, 0.f);
        int j = o0;
        for (; j + 1 < o1; j += 2) {
            int ed0 = __ldg(g_nedge + j), ed1 = __ldg(g_nedge + j + 1);
            float w0 = g_snp[j], w1 = g_snp[j + 1];
            float4 e0r = ((const float4*)(g_Xe1 + (size_t)ed0 * D))[lane];
            float4 e1r = ((const float4*)(g_Xe1 + (size_t)ed1 * D))[lane];
            acc.x = fmaf(e0r.x, w0, acc.x); acc.y = fmaf(e0r.y, w0, acc.y);
            acc.z = fmaf(e0r.z, w0, acc.z); acc.w = fmaf(e0r.w, w0, acc.w);
            acc2.x = fmaf(e1r.x, w1, acc2.x); acc2.y = fmaf(e1r.y, w1, acc2.y);
            acc2.z = fmaf(e1r.z, w1, acc2.z); acc2.w = fmaf(e1r.w, w1, acc2.w);
        }
        if (j < o1) {
            int ed = __ldg(g_nedge + j);
            float wn = g_snp[j];
            float4 xr = ((const float4*)(g_Xe1 + (size_t)ed * D))[lane];
            acc.x = fmaf(xr.x, wn, acc.x); acc.y = fmaf(xr.y, wn, acc.y);
            acc.z = fmaf(xr.z, wn, acc.z); acc.w = fmaf(xr.w, wn, acc.w);
        }
        float s = (o1 > o0) ? 1.f / g_denN[w] : 0.f;
        float sc = 0.45f * g_degV[w] * s;
        float4 v2 = ((const float4*)(g_Xv2 + (size_t)w * D))[lane];
        float4 x0 = ((const float4*)(g_x0 + (size_t)w * D))[lane];
        float4 r;
        r.x = sc * (acc.x + acc2.x) + 0.45f * v2.x + 0.1f * x0.x;
        r.y = sc * (acc.y + acc2.y) + 0.45f * v2.y + 0.1f * x0.y;
        r.z = sc * (acc.z + acc2.z) + 0.45f * v2.z + 0.1f * x0.z;
        r.w = sc * (acc.w + acc2.w) + 0.45f * v2.w + 0.1f * x0.w;
        split_store4(g_ah, g_al, w * 32 + lane, r);
    }
}

// ---------------- launch ----------------
extern "C" void kernel_launch(void* const* d_in, const int* in_sizes, int n_in,
                              void* d_out, int out_size) {
    const float* x_in = (const float*)d_in[0];
    const float* e_in = (const float*)d_in[1];
    const int*   hei  = (const int*)d_in[2];
    const int*   nodes = hei;
    const int*   edges = hei + NZ;
    const float* dv2e = (const float*)d_in[3];
    const float* gv2e = (const float*)d_in[4];
    const float* de2v = (const float*)d_in[5];
    const float* ge2v = (const float*)d_in[6];
    const float* W0   = (const float*)d_in[7];
    const float* b0   = (const float*)d_in[8];
    const float* Wn   = (const float*)d_in[9];
    const float* We   = (const float*)d_in[10];
    const float* aw   = (const float*)d_in[11];
    const float* ab   = (const float*)d_in[12];
    const float* wdw  = (const float*)d_in[13];
    const float* wdb  = (const float*)d_in[14];
    const float* wgw  = (const float*)d_in[15];
    const float* wgb  = (const float*)d_in[16];
    float* out = (float*)d_out;

    cudaFuncSetAttribute(k_gemm0, cudaFuncAttributeMaxDynamicSharedMemorySize, SMEM_MMA);
    cudaFuncSetAttribute(k_gemm2<1>, cudaFuncAttributeMaxDynamicSharedMemorySize, SMEM_MMA);
    cudaFuncSetAttribute(k_gemm2<2>, cudaFuncAttributeMaxDynamicSharedMemorySize, SMEM_MMA);

    void *pncnt;
    void *px, *px0, *pe, *psx1, *psx2, *pse1, *pse2;
    void *pah, *pal, *pebh, *pebl, *pw0h, *pw0l, *pwnh, *pwnl, *pweh, *pwel;
    cudaGetSymbolAddress(&pncnt, g_ncnt);
    cudaGetSymbolAddress(&px, g_x);       cudaGetSymbolAddress(&px0, g_x0);
    cudaGetSymbolAddress(&pe, g_e);
    cudaGetSymbolAddress(&psx1, g_sx1);   cudaGetSymbolAddress(&psx2, g_sx2);
    cudaGetSymbolAddress(&pse1, g_se1);   cudaGetSymbolAddress(&pse2, g_se2);
    cudaGetSymbolAddress(&pah, g_ah);     cudaGetSymbolAddress(&pal, g_al);
    cudaGetSymbolAddress(&pebh, g_ebh);   cudaGetSymbolAddress(&pebl, g_ebl);
    cudaGetSymbolAddress(&pw0h, g_w0h);   cudaGetSymbolAddress(&pw0l, g_w0l);
    cudaGetSymbolAddress(&pwnh, g_wnh);   cudaGetSymbolAddress(&pwnl, g_wnl);
    cudaGetSymbolAddress(&pweh, g_weh);   cudaGetSymbolAddress(&pwel, g_wel);

    const int B = 256;
    const int gNZ   = (NZ + B - 1) / B;
    const int gNN   = (NN + B - 1) / B;
    const int gEW   = (NE * 32 + B - 1) / B;
    const int gPASS = ((NE + NN) * 32 + B - 1) / B;
    const int gXT   = (NN + 63) / 64;
    const int gET   = (NE + 63) / 64;
    const int gCW   = ((1 + 2 * NL) * D * D + B - 1) / B;

    // ---- one-time setup ----
    cudaMemsetAsync(pncnt, 0, NN * 4, 0);
    k_count<<<gNZ, B>>>(nodes);
    k_eoff2<<<gNZ, B>>>(edges);
    k_degE<<<gEW, B>>>(nodes);
    k_scan1<<<SCAN_NBLK, SCAN_B>>>();
    k_scan2<<<1, 32>>>();
    k_scan3<<<gNN, B>>>();
    k_scatter<<<gNZ, B>>>(nodes, edges, de2v, ge2v);
    k_cvt_allw<<<gCW, B>>>(W0, Wn, We);

    k_cvt_rows<<<(NN * D / 4 + B - 1) / B, B>>>(x_in, (__nv_bfloat16*)pah, (__nv_bfloat16*)pal,
                                                NN * D / 4);
    k_gemm0<<<gXT, 256, SMEM_MMA>>>((__nv_bfloat16*)pah, (__nv_bfloat16*)pal,
                                    (__nv_bfloat16*)pw0h, (__nv_bfloat16*)pw0l,
                                    b0, (float*)px, (float*)px0, NN,
                                    aw, (float*)psx1, (float*)psx2);
    cudaMemcpyAsync(pe, e_in, (size_t)NE * D * 4, cudaMemcpyDeviceToDevice, 0);
    k_rowdot<<<(NE * 32 + B - 1) / B, B>>>(e_in, aw, aw + D, (float*)pse2, (float*)pse1, NE);

    bool both = (out_size >= (NN + NE) * D);

    for (int l = 0; l < NL; l++) {
        float beta = logf(0.5f / (float)(l + 1) + 1.f);

        k_pass1<<<gPASS, B>>>(nodes, dv2e, gv2e,
                              ab + l, wdw + l, wdb + l, wgw + l, wgb + l);
        k_pass2<<<gPASS, B>>>(nodes, e_in);

        GP gx, ge;
        gx.Ah = (__nv_bfloat16*)pah; gx.Al = (__nv_bfloat16*)pal;
        gx.Bh = (__nv_bfloat16*)pwnh + (size_t)l * D * D;
        gx.Bl = (__nv_bfloat16*)pwnl + (size_t)l * D * D;
        gx.M = NN; gx.nblk = gXT;
        gx.dlo = (float*)psx1; gx.dhi = (float*)psx2;
        ge.Ah = (__nv_bfloat16*)pebh; ge.Al = (__nv_bfloat16*)pebl;
        ge.Bh = (__nv_bfloat16*)pweh + (size_t)l * D * D;
        ge.Bl = (__nv_bfloat16*)pwel + (size_t)l * D * D;
        ge.M = NE; ge.nblk = gET;
        ge.dlo = (float*)pse2; ge.dhi = (float*)pse1;

        if (l < NL - 1) {
            gx.C = (float*)px;
            ge.C = (float*)pe;
            const float* awn = aw + (size_t)(l + 1) * 2 * D;
            k_gemm2<1><<<gXT + gET, 256, SMEM_MMA>>>(gx, ge, beta, awn);
        } else {
            gx.C = out;
            ge.C = both ? out + (size_t)NN * D : (float*)pe;
            k_gemm2<2><<<gXT + gET, 256, SMEM_MMA>>>(gx, ge, beta, nullptr);
        }
    }
}